// round 10
// baseline (speedup 1.0000x reference)
#include <cuda_runtime.h>
#include <cuda_bf16.h>
#include <math.h>
#include <stdint.h>

#define BATCH 2
#define NN 48
#define DMODEL 256
#define NHEAD 8
#define DHEAD 64
#define HD 512
#define FFDIM 1024
#define NLAYER 4
#define PDIM 32
#define NFEAT 20
#define NEFEAT 5
#define SLEN 2352
#define MTOT (BATCH*SLEN) // 4704

// ---------------- scratch ----------------
__device__ float g_X  [MTOT * DMODEL];
__device__ float g_QKV[MTOT * 3 * HD];
__device__ float g_AO [MTOT * HD];
__device__ float g_T  [MTOT * DMODEL];
__device__ float g_FF [MTOT * FFDIM];
__device__ float g_POS[BATCH * NN * PDIM];
__device__ float g_EDG[BATCH * NN * NN * NEFEAT];

// ---------------- tf32 helpers ----------------
__device__ __forceinline__ float to_tf32(float x) {
    uint32_t u;
    asm("cvt.rna.tf32.f32 %0, %1;" : "=r"(u) : "f"(x));
    return __uint_as_float(u);
}
__device__ __forceinline__ void mma_tf32(float c[4],
    float a0, float a1, float a2, float a3, float b0, float b1) {
    asm volatile(
        "mma.sync.aligned.m16n8k8.row.col.f32.tf32.tf32.f32 "
        "{%0,%1,%2,%3}, {%4,%5,%6,%7}, {%8,%9}, {%0,%1,%2,%3};"
        : "+f"(c[0]), "+f"(c[1]), "+f"(c[2]), "+f"(c[3])
        : "r"(__float_as_uint(a0)), "r"(__float_as_uint(a1)),
          "r"(__float_as_uint(a2)), "r"(__float_as_uint(a3)),
          "r"(__float_as_uint(b0)), "r"(__float_as_uint(b1)));
}
__device__ __forceinline__ int pperm(int k) {
    return (k & ~7) + 2 * (k & 3) + ((k >> 2) & 1);
}
__device__ __forceinline__ void store_perm4(float* row, int k, float4 v) {
    int base = (k & ~7) + ((k >> 2) & 1);
    row[base]     = to_tf32(v.x);
    row[base + 2] = to_tf32(v.y);
    row[base + 4] = to_tf32(v.z);
    row[base + 6] = to_tf32(v.w);
}

// ---------------- positional encoding * perm ----------------
__global__ void k_pos(const float* __restrict__ perm) {
    int b = blockIdx.x / NN, i = blockIdx.x % NN;
    int d = threadIdx.x;
    int k = d >> 1;
    float div = expf(-logf(10000.0f) * (2.0f * (float)k) / (float)PDIM);
    float acc = 0.0f;
    for (int j = 0; j < NN; j++) {
        float ang = (float)j * div;
        float pe = (d & 1) ? cosf(ang) : sinf(ang);
        acc += perm[(b * NN + i) * NN + j] * pe;
    }
    g_POS[(b * NN + i) * PDIM + d] = acc;
}

// ---------------- build initial x ----------------
__global__ void k_build_x(const float* __restrict__ graph_emb,
                          const float* __restrict__ pn_w, const float* __restrict__ pn_b,
                          const float* __restrict__ pe_w, const float* __restrict__ pe_b) {
    int t = blockIdx.x;
    int b = t / SLEN, s = t % SLEN;
    int d = threadIdx.x;
    __shared__ float pi[PDIM], pj[PDIM];
    if (s < NN) {
        if (threadIdx.x < PDIM) pi[threadIdx.x] = g_POS[(b * NN + s) * PDIM + threadIdx.x];
    } else {
        int e = s - NN;
        int i = e / NN, j = e % NN;
        if (threadIdx.x < PDIM) pi[threadIdx.x] = g_POS[(b * NN + i) * PDIM + threadIdx.x];
        else if (threadIdx.x < 2 * PDIM) pj[threadIdx.x - PDIM] = g_POS[(b * NN + j) * PDIM + threadIdx.x - PDIM];
    }
    __syncthreads();
    float acc = graph_emb[b * DMODEL + d];
    if (s < NN) {
        acc += pn_b[d];
        #pragma unroll 8
        for (int p = 0; p < PDIM; p++) acc += pi[p] * pn_w[p * DMODEL + d];
    } else {
        acc += pe_b[d];
        #pragma unroll 8
        for (int p = 0; p < PDIM; p++) {
            acc += pi[p] * pe_w[p * DMODEL + d];
            acc += pj[p] * pe_w[(PDIM + p) * DMODEL + d];
        }
    }
    g_X[(size_t)t * DMODEL + d] = acc;
}

// ---------------- tf32 GEMM, double-buffered, pair-permuted ----------------
#define GBM 128
#define GBN 64
#define GBK 32
#define GSTR 36
#define GSBUF ((GBM + GBN) * GSTR)
__global__ __launch_bounds__(256, 2) void k_gemm(
    const float* __restrict__ A,
    const float* __restrict__ W0, const float* __restrict__ W1, const float* __restrict__ W2,
    const float* __restrict__ B0, const float* __restrict__ B1, const float* __restrict__ B2,
    float* __restrict__ C, int M, int Kin, int Nper, int Nstride, int relu) {
    extern __shared__ float sm[];
    int m0 = blockIdx.x * GBM, n0 = blockIdx.y * GBN;
    int sel = n0 / Nper, nw = n0 % Nper;
    const float* W    = (sel == 0) ? W0 : (sel == 1) ? W1 : W2;
    const float* bias = (sel == 0) ? B0 : (sel == 1) ? B1 : B2;
    int tid = threadIdx.x, lane = tid & 31, wid = tid >> 5;
    int wm = (wid & 3) * 32, wn = (wid >> 2) * 32;
    float c[2][4][4] = {};

    int ar = tid >> 3, ak = (tid & 7) * 4;
    int bk = tid & 31, bnb = (tid >> 5) * 8;

    float4 aR[4], bR0, bR1;
    int nk = Kin / GBK;

    auto gload = [&](int k0) {
        #pragma unroll
        for (int p = 0; p < 4; p++) {
            int row = m0 + ar + p * 32;
            aR[p] = (row < M) ? *(const float4*)(A + (size_t)row * Kin + k0 + ak)
                              : make_float4(0.f, 0.f, 0.f, 0.f);
        }
        const float* wp = W + (size_t)(k0 + bk) * Nper + nw + bnb;
        bR0 = *(const float4*)(wp);
        bR1 = *(const float4*)(wp + 4);
    };
    auto sstore = [&](int s) {
        float* sA = sm + s * GSBUF;
        float* sB = sA + GBM * GSTR;
        #pragma unroll
        for (int p = 0; p < 4; p++)
            store_perm4(&sA[(ar + p * 32) * GSTR], ak, aR[p]);
        int pk = pperm(bk);
        sB[(bnb + 0) * GSTR + pk] = to_tf32(bR0.x);
        sB[(bnb + 1) * GSTR + pk] = to_tf32(bR0.y);
        sB[(bnb + 2) * GSTR + pk] = to_tf32(bR0.z);
        sB[(bnb + 3) * GSTR + pk] = to_tf32(bR0.w);
        sB[(bnb + 4) * GSTR + pk] = to_tf32(bR1.x);
        sB[(bnb + 5) * GSTR + pk] = to_tf32(bR1.y);
        sB[(bnb + 6) * GSTR + pk] = to_tf32(bR1.z);
        sB[(bnb + 7) * GSTR + pk] = to_tf32(bR1.w);
    };

    gload(0);
    sstore(0);
    __syncthreads();

    for (int t = 0; t < nk; t++) {
        if (t + 1 < nk) gload((t + 1) * GBK);
        int s = t & 1;
        const float* sA = sm + s * GSBUF;
        const float* sB = sA + GBM * GSTR;
        #pragma unroll
        for (int kb = 0; kb < GBK; kb += 8) {
            float2 ap[4];
            #pragma unroll
            for (int i = 0; i < 4; i++)
                ap[i] = *(const float2*)&sA[(wm + (lane >> 2) + i * 8) * GSTR + kb + 2 * (lane & 3)];
            #pragma unroll
            for (int j = 0; j < 4; j++) {
                float2 bp = *(const float2*)&sB[(wn + j * 8 + (lane >> 2)) * GSTR + kb + 2 * (lane & 3)];
                mma_tf32(c[0][j], ap[0].x, ap[1].x, ap[0].y, ap[1].y, bp.x, bp.y);
                mma_tf32(c[1][j], ap[2].x, ap[3].x, ap[2].y, ap[3].y, bp.x, bp.y);
            }
        }
        if (t + 1 < nk) sstore(s ^ 1);
        __syncthreads();
    }

    #pragma unroll
    for (int i = 0; i < 2; i++) {
        int r0 = m0 + wm + i * 16 + (lane >> 2);
        #pragma unroll
        for (int j = 0; j < 4; j++) {
            int col = wn + j * 8 + 2 * (lane & 3);
            float b0 = bias[nw + col], b1 = bias[nw + col + 1];
            float v0 = c[i][j][0] + b0, v1 = c[i][j][1] + b1;
            float v2 = c[i][j][2] + b0, v3 = c[i][j][3] + b1;
            if (relu) { v0 = fmaxf(v0, 0.f); v1 = fmaxf(v1, 0.f); v2 = fmaxf(v2, 0.f); v3 = fmaxf(v3, 0.f); }
            if (r0 < M) { float2 o = {v0, v1}; *(float2*)(C + (size_t)r0 * Nstride + n0 + col) = o; }
            if (r0 + 8 < M) { float2 o = {v2, v3}; *(float2*)(C + (size_t)(r0 + 8) * Nstride + n0 + col) = o; }
        }
    }
}

// ---------------- flash attention v4: register P via quad-shuffle ----------------
#define QT 128
#define FST 68
#define FSC (0.125f * 1.44269504088896340736f)
__global__ __launch_bounds__(128, 3) void k_flash(const float* __restrict__ QKV,
                                                  float* __restrict__ AO) {
    extern __shared__ float sm[];
    float* sQ  = sm;                       // [128][68] pair-perm over d
    float* sK  = sQ  + QT * FST;           // [64 key][68] pair-perm over d
    float* sVT = sK  + 64 * FST;           // [64 d][68] pair-perm over key

    int b = blockIdx.z, h = blockIdx.y;
    int q0 = blockIdx.x * QT;
    int tid = threadIdx.x, lane = tid & 31, wid = tid >> 5;
    int wr = wid * 32;

    // shuffle constants for C-frag -> A-frag conversion (loop-invariant)
    int qbase = lane & 28;
    int src  = qbase + ((lane & 3) >> 1);
    int src2 = src + 2;
    bool par = lane & 1;

    // load Q tile: 1 row per thread
    {
        int qi = q0 + tid;
        bool v = qi < SLEN;
        const float* Qp = QKV + ((size_t)(b * SLEN + (v ? qi : 0))) * 1536 + h * DHEAD;
        float* row = &sQ[tid * FST];
        #pragma unroll
        for (int i = 0; i < 16; i++) {
            float4 q4 = v ? *(const float4*)(Qp + i * 4) : make_float4(0.f, 0.f, 0.f, 0.f);
            store_perm4(row, i * 4, q4);
        }
    }

    float o[2][8][4] = {};
    float mrow[2][2] = {{-1e30f, -1e30f}, {-1e30f, -1e30f}};
    float lrow[2][2] = {{0.f, 0.f}, {0.f, 0.f}};

    for (int k0 = 0; k0 < SLEN; k0 += 64) {
        __syncthreads();
        // stage K and V^T
        {
            int row = tid >> 1, half = tid & 1;
            int ki = k0 + row;
            bool v = ki < SLEN;
            const float* Kp = QKV + ((size_t)(b * SLEN + (v ? ki : 0))) * 1536 + HD + h * DHEAD + half * 32;
            const float* Vp = Kp + HD;
            float* krow = &sK[row * FST];
            int pk = pperm(row);
            #pragma unroll
            for (int i = 0; i < 8; i++) {
                int d = half * 32 + i * 4;
                float4 kv = v ? *(const float4*)(Kp + i * 4) : make_float4(0.f, 0.f, 0.f, 0.f);
                store_perm4(krow, d, kv);
                float4 vv = v ? *(const float4*)(Vp + i * 4) : make_float4(0.f, 0.f, 0.f, 0.f);
                sVT[(d + 0) * FST + pk] = to_tf32(vv.x);
                sVT[(d + 1) * FST + pk] = to_tf32(vv.y);
                sVT[(d + 2) * FST + pk] = to_tf32(vv.z);
                sVT[(d + 3) * FST + pk] = to_tf32(vv.w);
            }
        }
        __syncthreads();

        // QK^T: 32 rows x 64 keys per warp
        float sc[2][8][4] = {};
        #pragma unroll
        for (int kb = 0; kb < 64; kb += 8) {
            float2 ap[4];
            #pragma unroll
            for (int i = 0; i < 4; i++)
                ap[i] = *(const float2*)&sQ[(wr + (lane >> 2) + i * 8) * FST + kb + 2 * (lane & 3)];
            #pragma unroll
            for (int j = 0; j < 8; j++) {
                float2 bp = *(const float2*)&sK[(j * 8 + (lane >> 2)) * FST + kb + 2 * (lane & 3)];
                mma_tf32(sc[0][j], ap[0].x, ap[1].x, ap[0].y, ap[1].y, bp.x, bp.y);
                mma_tf32(sc[1][j], ap[2].x, ap[3].x, ap[2].y, ap[3].y, bp.x, bp.y);
            }
        }

        // softmax in registers; convert C-frag P -> A-frag P via quad shuffles
        bool tail = (k0 + 64 > SLEN);
        #pragma unroll
        for (int i = 0; i < 2; i++) {
            float mx0 = -1e30f, mx1 = -1e30f;
            #pragma unroll
            for (int j = 0; j < 8; j++) {
                int col = j * 8 + 2 * (lane & 3);
                float s0 = sc[i][j][0] * FSC, s1 = sc[i][j][1] * FSC;
                float s2 = sc[i][j][2] * FSC, s3 = sc[i][j][3] * FSC;
                if (tail) {
                    if (k0 + col >= SLEN)     { s0 = -1e30f; s2 = -1e30f; }
                    if (k0 + col + 1 >= SLEN) { s1 = -1e30f; s3 = -1e30f; }
                }
                sc[i][j][0] = s0; sc[i][j][1] = s1; sc[i][j][2] = s2; sc[i][j][3] = s3;
                mx0 = fmaxf(mx0, fmaxf(s0, s1));
                mx1 = fmaxf(mx1, fmaxf(s2, s3));
            }
            mx0 = fmaxf(mx0, __shfl_xor_sync(0xffffffffu, mx0, 1));
            mx0 = fmaxf(mx0, __shfl_xor_sync(0xffffffffu, mx0, 2));
            mx1 = fmaxf(mx1, __shfl_xor_sync(0xffffffffu, mx1, 1));
            mx1 = fmaxf(mx1, __shfl_xor_sync(0xffffffffu, mx1, 2));
            float mn0 = fmaxf(mrow[i][0], mx0);
            float mn1 = fmaxf(mrow[i][1], mx1);
            float sf0 = exp2f(mrow[i][0] - mn0);
            float sf1 = exp2f(mrow[i][1] - mn1);
            mrow[i][0] = mn0; mrow[i][1] = mn1;
            float sum0 = 0.f, sum1 = 0.f;
            #pragma unroll
            for (int j = 0; j < 8; j++) {
                float p0 = exp2f(sc[i][j][0] - mn0);
                float p1 = exp2f(sc[i][j][1] - mn0);
                float p2 = exp2f(sc[i][j][2] - mn1);
                float p3 = exp2f(sc[i][j][3] - mn1);
                sum0 += p0 + p1;
                sum1 += p2 + p3;
                // convert to A-fragment: a0=(r,c) a1=(r+8,c) a2=(r,c+4) a3=(r+8,c+4)
                float v0 = __shfl_sync(0xffffffffu, p0, src);
                float v1 = __shfl_sync(0xffffffffu, p1, src);
                float v2 = __shfl_sync(0xffffffffu, p2, src);
                float v3 = __shfl_sync(0xffffffffu, p3, src);
                float w0 = __shfl_sync(0xffffffffu, p0, src2);
                float w1 = __shfl_sync(0xffffffffu, p1, src2);
                float w2 = __shfl_sync(0xffffffffu, p2, src2);
                float w3 = __shfl_sync(0xffffffffu, p3, src2);
                sc[i][j][0] = to_tf32(par ? v1 : v0);
                sc[i][j][1] = to_tf32(par ? v3 : v2);
                sc[i][j][2] = to_tf32(par ? w1 : w0);
                sc[i][j][3] = to_tf32(par ? w3 : w2);
                o[i][j][0] *= sf0; o[i][j][1] *= sf0;
                o[i][j][2] *= sf1; o[i][j][3] *= sf1;
            }
            sum0 += __shfl_xor_sync(0xffffffffu, sum0, 1);
            sum0 += __shfl_xor_sync(0xffffffffu, sum0, 2);
            sum1 += __shfl_xor_sync(0xffffffffu, sum1, 1);
            sum1 += __shfl_xor_sync(0xffffffffu, sum1, 2);
            lrow[i][0] = lrow[i][0] * sf0 + sum0;
            lrow[i][1] = lrow[i][1] * sf1 + sum1;
        }

        // O += P @ V  (P A-frags live in sc registers)
        #pragma unroll
        for (int kb = 0; kb < 8; kb++) {
            #pragma unroll
            for (int j = 0; j < 8; j++) {
                float2 bp = *(const float2*)&sVT[(j * 8 + (lane >> 2)) * FST + kb * 8 + 2 * (lane & 3)];
                mma_tf32(o[0][j], sc[0][kb][0], sc[0][kb][1], sc[0][kb][2], sc[0][kb][3], bp.x, bp.y);
                mma_tf32(o[1][j], sc[1][kb][0], sc[1][kb][1], sc[1][kb][2], sc[1][kb][3], bp.x, bp.y);
            }
        }
    }

    // normalize + store
    #pragma unroll
    for (int i = 0; i < 2; i++) {
        int rl = wr + 16 * i + (lane >> 2);
        int q1 = q0 + rl, q2 = q1 + 8;
        float inv0 = 1.f / lrow[i][0];
        float inv1 = 1.f / lrow[i][1];
        #pragma unroll
        for (int j = 0; j < 8; j++) {
            int col = h * DHEAD + j * 8 + 2 * (lane & 3);
            if (q1 < SLEN) {
                float2 v = {o[i][j][0] * inv0, o[i][j][1] * inv0};
                *(float2*)(AO + ((size_t)(b * SLEN + q1)) * HD + col) = v;
            }
            if (q2 < SLEN) {
                float2 v = {o[i][j][2] * inv1, o[i][j][3] * inv1};
                *(float2*)(AO + ((size_t)(b * SLEN + q2)) * HD + col) = v;
            }
        }
    }
}

// ---------------- residual + layernorm (single-pass, warp reductions) ----------------
__global__ void k_lnres(const float* __restrict__ delta,
                        const float* __restrict__ gw, const float* __restrict__ bw) {
    int t = blockIdx.x;
    int d = threadIdx.x;
    int lane = d & 31, warp = d >> 5;
    __shared__ float ws[8], ws2[8];
    float v = g_X[(size_t)t * DMODEL + d] + delta[(size_t)t * DMODEL + d];
    float s = v, s2 = v * v;
    #pragma unroll
    for (int off = 16; off > 0; off >>= 1) {
        s  += __shfl_xor_sync(0xffffffffu, s, off);
        s2 += __shfl_xor_sync(0xffffffffu, s2, off);
    }
    if (lane == 0) { ws[warp] = s; ws2[warp] = s2; }
    __syncthreads();
    float ts = 0.f, ts2 = 0.f;
    #pragma unroll
    for (int w = 0; w < 8; w++) { ts += ws[w]; ts2 += ws2[w]; }
    float mean = ts * (1.0f / DMODEL);
    float var = ts2 * (1.0f / DMODEL) - mean * mean;
    g_X[(size_t)t * DMODEL + d] = (v - mean) * rsqrtf(var + 1e-5f) * gw[d] + bw[d];
}

// ---------------- output heads ----------------
__global__ void k_node_out(const float* __restrict__ w, const float* __restrict__ bias,
                           float* __restrict__ out) {
    int t = blockIdx.x;
    int b = t / NN, i = t % NN;
    __shared__ float row[DMODEL];
    row[threadIdx.x] = g_X[((size_t)(b * SLEN + i)) * DMODEL + threadIdx.x];
    __syncthreads();
    if (threadIdx.x < NFEAT) {
        float acc = bias[threadIdx.x];
        for (int d = 0; d < DMODEL; d++) acc += row[d] * w[d * NFEAT + threadIdx.x];
        out[t * NFEAT + threadIdx.x] = acc;
    }
}

__global__ void k_edge_pre(const float* __restrict__ w, const float* __restrict__ bias) {
    int t = blockIdx.x;
    int b = t / (NN * NN), e = t % (NN * NN);
    __shared__ float row[DMODEL];
    row[threadIdx.x] = g_X[((size_t)(b * SLEN + NN + e)) * DMODEL + threadIdx.x];
    __syncthreads();
    if (threadIdx.x < NEFEAT) {
        float acc = bias[threadIdx.x];
        for (int d = 0; d < DMODEL; d++) acc += row[d] * w[d * NEFEAT + threadIdx.x];
        g_EDG[t * NEFEAT + threadIdx.x] = acc;
    }
}

__global__ void k_edge_sym(float* __restrict__ out) {
    int idx = blockIdx.x * 256 + threadIdx.x;
    const int total = BATCH * NN * NN * NEFEAT;
    if (idx >= total) return;
    int f = idx % NEFEAT;
    int r = idx / NEFEAT;
    int j = r % NN; r /= NN;
    int i = r % NN;
    int b = r / NN;
    float a = g_EDG[(((b * NN + i) * NN + j)) * NEFEAT + f];
    float c = g_EDG[(((b * NN + j) * NN + i)) * NEFEAT + f];
    out[BATCH * NN * NFEAT + idx] = 0.5f * (a + c);
}

// ---------------- launcher ----------------
extern "C" void kernel_launch(void* const* d_in, const int* in_sizes, int n_in,
                              void* d_out, int out_size) {
    const float* graph_emb = (const float*)d_in[0];
    const float* perm      = (const float*)d_in[1];
    const float* pn_w = (const float*)d_in[3];
    const float* pn_b = (const float*)d_in[4];
    const float* pe_w = (const float*)d_in[5];
    const float* pe_b = (const float*)d_in[6];
    const float* no_w = (const float*)d_in[7];
    const float* no_b = (const float*)d_in[8];
    const float* eo_w = (const float*)d_in[9];
    const float* eo_b = (const float*)d_in[10];
    const float* Wq = (const float*)d_in[11];
    const float* bq = (const float*)d_in[12];
    const float* Wk = (const float*)d_in[13];
    const float* bk = (const float*)d_in[14];
    const float* Wv = (const float*)d_in[15];
    const float* bv = (const float*)d_in[16];
    const float* Wo = (const float*)d_in[17];
    const float* bo = (const float*)d_in[18];
    const float* W1 = (const float*)d_in[19];
    const float* b1 = (const float*)d_in[20];
    const float* W2 = (const float*)d_in[21];
    const float* b2 = (const float*)d_in[22];
    const float* ln1g = (const float*)d_in[23];
    const float* ln1b = (const float*)d_in[24];
    const float* ln2g = (const float*)d_in[25];
    const float* ln2b = (const float*)d_in[26];
    float* out = (float*)d_out;

    float *pX, *pQKV, *pAO, *pT, *pFF;
    cudaGetSymbolAddress((void**)&pX,   g_X);
    cudaGetSymbolAddress((void**)&pQKV, g_QKV);
    cudaGetSymbolAddress((void**)&pAO,  g_AO);
    cudaGetSymbolAddress((void**)&pT,   g_T);
    cudaGetSymbolAddress((void**)&pFF,  g_FF);

    const int gemm_smem  = 2 * GSBUF * (int)sizeof(float);
    const int flash_smem = (QT + 64 + 64) * FST * (int)sizeof(float);
    cudaFuncSetAttribute(k_gemm,  cudaFuncAttributeMaxDynamicSharedMemorySize, gemm_smem);
    cudaFuncSetAttribute(k_flash, cudaFuncAttributeMaxDynamicSharedMemorySize, flash_smem);

    k_pos<<<BATCH * NN, PDIM>>>(perm);
    k_build_x<<<MTOT, DMODEL>>>(graph_emb, pn_w, pn_b, pe_w, pe_b);

    const int M = MTOT;
    const int MG = (M + GBM - 1) / GBM;   // 37
    dim3 gQKV(MG, (3 * HD) / GBN);        // 37 x 24
    dim3 gO  (MG, DMODEL / GBN);          // 37 x 4
    dim3 gF1 (MG, FFDIM / GBN);           // 37 x 16
    dim3 gAtt((SLEN + QT - 1) / QT, NHEAD, BATCH);   // 19 x 8 x 2

    for (int l = 0; l < NLAYER; l++) {
        const float* Wql = Wq + (size_t)l * DMODEL * HD;
        const float* Wkl = Wk + (size_t)l * DMODEL * HD;
        const float* Wvl = Wv + (size_t)l * DMODEL * HD;
        const float* Wol = Wo + (size_t)l * HD * DMODEL;
        const float* W1l = W1 + (size_t)l * DMODEL * FFDIM;
        const float* W2l = W2 + (size_t)l * FFDIM * DMODEL;

        k_gemm<<<gQKV, 256, gemm_smem>>>(pX, Wql, Wkl, Wvl,
                                         bq + l * HD, bk + l * HD, bv + l * HD,
                                         pQKV, M, DMODEL, HD, 3 * HD, 0);
        k_flash<<<gAtt, 128, flash_smem>>>(pQKV, pAO);
        k_gemm<<<gO, 256, gemm_smem>>>(pAO, Wol, Wol, Wol,
                                       bo + l * DMODEL, bo + l * DMODEL, bo + l * DMODEL,
                                       pT, M, HD, DMODEL, DMODEL, 0);
        k_lnres<<<MTOT, DMODEL>>>(pT, ln1g + l * DMODEL, ln1b + l * DMODEL);
        k_gemm<<<gF1, 256, gemm_smem>>>(pX, W1l, W1l, W1l,
                                        b1 + l * FFDIM, b1 + l * FFDIM, b1 + l * FFDIM,
                                        pFF, M, DMODEL, FFDIM, FFDIM, 1);
        k_gemm<<<gO, 256, gemm_smem>>>(pFF, W2l, W2l, W2l,
                                       b2 + l * DMODEL, b2 + l * DMODEL, b2 + l * DMODEL,
                                       pT, M, FFDIM, DMODEL, DMODEL, 0);
        k_lnres<<<MTOT, DMODEL>>>(pT, ln2g + l * DMODEL, ln2b + l * DMODEL);
    }

    k_node_out<<<BATCH * NN, DMODEL>>>(no_w, no_b, out);
    k_edge_pre<<<BATCH * NN * NN, DMODEL>>>(eo_w, eo_b);
    k_edge_sym<<<(BATCH * NN * NN * NEFEAT + 255) / 256, 256>>>(out);
}

// round 11
// speedup vs baseline: 1.4688x; 1.4688x over previous
#include <cuda_runtime.h>
#include <cuda_bf16.h>
#include <math.h>
#include <stdint.h>

#define BATCH 2
#define NN 48
#define DMODEL 256
#define NHEAD 8
#define DHEAD 64
#define HD 512
#define FFDIM 1024
#define NLAYER 4
#define PDIM 32
#define NFEAT 20
#define NEFEAT 5
#define SLEN 2352
#define MTOT (BATCH*SLEN) // 4704

// ---------------- scratch ----------------
__device__ float g_X  [MTOT * DMODEL];
__device__ float g_QKV[MTOT * 3 * HD];
__device__ float g_AO [MTOT * HD];
__device__ float g_T  [MTOT * DMODEL];
__device__ float g_FF [MTOT * FFDIM];
__device__ float g_POS[BATCH * NN * PDIM];
__device__ float g_EDG[BATCH * NN * NN * NEFEAT];

// ---------------- tf32 helpers ----------------
__device__ __forceinline__ float to_tf32(float x) {
    uint32_t u;
    asm("cvt.rna.tf32.f32 %0, %1;" : "=r"(u) : "f"(x));
    return __uint_as_float(u);
}
__device__ __forceinline__ void mma_tf32(float c[4],
    float a0, float a1, float a2, float a3, float b0, float b1) {
    asm volatile(
        "mma.sync.aligned.m16n8k8.row.col.f32.tf32.tf32.f32 "
        "{%0,%1,%2,%3}, {%4,%5,%6,%7}, {%8,%9}, {%0,%1,%2,%3};"
        : "+f"(c[0]), "+f"(c[1]), "+f"(c[2]), "+f"(c[3])
        : "r"(__float_as_uint(a0)), "r"(__float_as_uint(a1)),
          "r"(__float_as_uint(a2)), "r"(__float_as_uint(a3)),
          "r"(__float_as_uint(b0)), "r"(__float_as_uint(b1)));
}
__device__ __forceinline__ int pperm(int k) {
    return (k & ~7) + 2 * (k & 3) + ((k >> 2) & 1);
}
__device__ __forceinline__ void store_perm4(float* row, int k, float4 v) {
    int base = (k & ~7) + ((k >> 2) & 1);
    row[base]     = to_tf32(v.x);
    row[base + 2] = to_tf32(v.y);
    row[base + 4] = to_tf32(v.z);
    row[base + 6] = to_tf32(v.w);
}

// ---------------- positional encoding * perm ----------------
__global__ void k_pos(const float* __restrict__ perm) {
    int b = blockIdx.x / NN, i = blockIdx.x % NN;
    int d = threadIdx.x;
    int k = d >> 1;
    float div = expf(-logf(10000.0f) * (2.0f * (float)k) / (float)PDIM);
    float acc = 0.0f;
    for (int j = 0; j < NN; j++) {
        float ang = (float)j * div;
        float pe = (d & 1) ? cosf(ang) : sinf(ang);
        acc += perm[(b * NN + i) * NN + j] * pe;
    }
    g_POS[(b * NN + i) * PDIM + d] = acc;
}

// ---------------- build initial x ----------------
__global__ void k_build_x(const float* __restrict__ graph_emb,
                          const float* __restrict__ pn_w, const float* __restrict__ pn_b,
                          const float* __restrict__ pe_w, const float* __restrict__ pe_b) {
    int t = blockIdx.x;
    int b = t / SLEN, s = t % SLEN;
    int d = threadIdx.x;
    __shared__ float pi[PDIM], pj[PDIM];
    if (s < NN) {
        if (threadIdx.x < PDIM) pi[threadIdx.x] = g_POS[(b * NN + s) * PDIM + threadIdx.x];
    } else {
        int e = s - NN;
        int i = e / NN, j = e % NN;
        if (threadIdx.x < PDIM) pi[threadIdx.x] = g_POS[(b * NN + i) * PDIM + threadIdx.x];
        else if (threadIdx.x < 2 * PDIM) pj[threadIdx.x - PDIM] = g_POS[(b * NN + j) * PDIM + threadIdx.x - PDIM];
    }
    __syncthreads();
    float acc = graph_emb[b * DMODEL + d];
    if (s < NN) {
        acc += pn_b[d];
        #pragma unroll 8
        for (int p = 0; p < PDIM; p++) acc += pi[p] * pn_w[p * DMODEL + d];
    } else {
        acc += pe_b[d];
        #pragma unroll 8
        for (int p = 0; p < PDIM; p++) {
            acc += pi[p] * pe_w[p * DMODEL + d];
            acc += pj[p] * pe_w[(PDIM + p) * DMODEL + d];
        }
    }
    g_X[(size_t)t * DMODEL + d] = acc;
}

// ---------------- tf32 GEMM, double-buffered, pair-permuted ----------------
#define GBM 128
#define GBN 64
#define GBK 32
#define GSTR 36
#define GSBUF ((GBM + GBN) * GSTR)
__global__ __launch_bounds__(256, 2) void k_gemm(
    const float* __restrict__ A,
    const float* __restrict__ W0, const float* __restrict__ W1, const float* __restrict__ W2,
    const float* __restrict__ B0, const float* __restrict__ B1, const float* __restrict__ B2,
    float* __restrict__ C, int M, int Kin, int Nper, int Nstride, int relu) {
    extern __shared__ float sm[];
    int m0 = blockIdx.x * GBM, n0 = blockIdx.y * GBN;
    int sel = n0 / Nper, nw = n0 % Nper;
    const float* W    = (sel == 0) ? W0 : (sel == 1) ? W1 : W2;
    const float* bias = (sel == 0) ? B0 : (sel == 1) ? B1 : B2;
    int tid = threadIdx.x, lane = tid & 31, wid = tid >> 5;
    int wm = (wid & 3) * 32, wn = (wid >> 2) * 32;
    float c[2][4][4] = {};

    int ar = tid >> 3, ak = (tid & 7) * 4;
    int bk = tid & 31, bnb = (tid >> 5) * 8;

    float4 aR[4], bR0, bR1;
    int nk = Kin / GBK;

    auto gload = [&](int k0) {
        #pragma unroll
        for (int p = 0; p < 4; p++) {
            int row = m0 + ar + p * 32;
            aR[p] = (row < M) ? *(const float4*)(A + (size_t)row * Kin + k0 + ak)
                              : make_float4(0.f, 0.f, 0.f, 0.f);
        }
        const float* wp = W + (size_t)(k0 + bk) * Nper + nw + bnb;
        bR0 = *(const float4*)(wp);
        bR1 = *(const float4*)(wp + 4);
    };
    auto sstore = [&](int s) {
        float* sA = sm + s * GSBUF;
        float* sB = sA + GBM * GSTR;
        #pragma unroll
        for (int p = 0; p < 4; p++)
            store_perm4(&sA[(ar + p * 32) * GSTR], ak, aR[p]);
        int pk = pperm(bk);
        sB[(bnb + 0) * GSTR + pk] = to_tf32(bR0.x);
        sB[(bnb + 1) * GSTR + pk] = to_tf32(bR0.y);
        sB[(bnb + 2) * GSTR + pk] = to_tf32(bR0.z);
        sB[(bnb + 3) * GSTR + pk] = to_tf32(bR0.w);
        sB[(bnb + 4) * GSTR + pk] = to_tf32(bR1.x);
        sB[(bnb + 5) * GSTR + pk] = to_tf32(bR1.y);
        sB[(bnb + 6) * GSTR + pk] = to_tf32(bR1.z);
        sB[(bnb + 7) * GSTR + pk] = to_tf32(bR1.w);
    };

    gload(0);
    sstore(0);
    __syncthreads();

    for (int t = 0; t < nk; t++) {
        if (t + 1 < nk) gload((t + 1) * GBK);
        int s = t & 1;
        const float* sA = sm + s * GSBUF;
        const float* sB = sA + GBM * GSTR;
        #pragma unroll
        for (int kb = 0; kb < GBK; kb += 8) {
            float2 ap[4];
            #pragma unroll
            for (int i = 0; i < 4; i++)
                ap[i] = *(const float2*)&sA[(wm + (lane >> 2) + i * 8) * GSTR + kb + 2 * (lane & 3)];
            #pragma unroll
            for (int j = 0; j < 4; j++) {
                float2 bp = *(const float2*)&sB[(wn + j * 8 + (lane >> 2)) * GSTR + kb + 2 * (lane & 3)];
                mma_tf32(c[0][j], ap[0].x, ap[1].x, ap[0].y, ap[1].y, bp.x, bp.y);
                mma_tf32(c[1][j], ap[2].x, ap[3].x, ap[2].y, ap[3].y, bp.x, bp.y);
            }
        }
        if (t + 1 < nk) sstore(s ^ 1);
        __syncthreads();
    }

    #pragma unroll
    for (int i = 0; i < 2; i++) {
        int r0 = m0 + wm + i * 16 + (lane >> 2);
        #pragma unroll
        for (int j = 0; j < 4; j++) {
            int col = wn + j * 8 + 2 * (lane & 3);
            float b0 = bias[nw + col], b1 = bias[nw + col + 1];
            float v0 = c[i][j][0] + b0, v1 = c[i][j][1] + b1;
            float v2 = c[i][j][2] + b0, v3 = c[i][j][3] + b1;
            if (relu) { v0 = fmaxf(v0, 0.f); v1 = fmaxf(v1, 0.f); v2 = fmaxf(v2, 0.f); v3 = fmaxf(v3, 0.f); }
            if (r0 < M) { float2 o = {v0, v1}; *(float2*)(C + (size_t)r0 * Nstride + n0 + col) = o; }
            if (r0 + 8 < M) { float2 o = {v2, v3}; *(float2*)(C + (size_t)(r0 + 8) * Nstride + n0 + col) = o; }
        }
    }
}

// ---------------- flash attention v5: R6 dataflow, 8 warps x 16 rows ----------------
#define QT 128
#define FST 68
#define FSC (0.125f * 1.44269504088896340736f)
__global__ __launch_bounds__(256, 2) void k_flash(const float* __restrict__ QKV,
                                                  float* __restrict__ AO) {
    extern __shared__ float sm[];
    float* sQ  = sm;                       // [128][68] pair-perm over d
    float* sK  = sQ  + QT * FST;           // [64 key][68] pair-perm over d
    float* sVT = sK  + 64 * FST;           // [64 d][68] pair-perm over key
    float* sP  = sVT + 64 * FST;           // [8][16][68] pair-perm over key

    int b = blockIdx.z, h = blockIdx.y;
    int q0 = blockIdx.x * QT;
    int tid = threadIdx.x, lane = tid & 31, wid = tid >> 5;   // 8 warps
    int wr = wid * 16;
    float* sPw = sP + wr * FST;

    // load Q tile: half a row per thread (256 threads, 128 rows)
    {
        int qr = tid >> 1, half = tid & 1;
        int qi = q0 + qr;
        bool v = qi < SLEN;
        const float* Qp = QKV + ((size_t)(b * SLEN + (v ? qi : 0))) * 1536 + h * DHEAD + half * 32;
        float* row = &sQ[qr * FST];
        #pragma unroll
        for (int i = 0; i < 8; i++) {
            float4 q4 = v ? *(const float4*)(Qp + i * 4) : make_float4(0.f, 0.f, 0.f, 0.f);
            store_perm4(row, half * 32 + i * 4, q4);
        }
    }

    float o[8][4] = {};
    float mrow[2] = {-1e30f, -1e30f};
    float lrow[2] = {0.f, 0.f};

    for (int k0 = 0; k0 < SLEN; k0 += 64) {
        __syncthreads();
        // stage K and V^T: quarter row per thread (256 threads, 64 rows)
        {
            int row = tid >> 2, quar = tid & 3;
            int ki = k0 + row;
            bool v = ki < SLEN;
            const float* Kp = QKV + ((size_t)(b * SLEN + (v ? ki : 0))) * 1536 + HD + h * DHEAD + quar * 16;
            const float* Vp = Kp + HD;
            float* krow = &sK[row * FST];
            int pk = pperm(row);
            #pragma unroll
            for (int i = 0; i < 4; i++) {
                int d = quar * 16 + i * 4;
                float4 kv = v ? *(const float4*)(Kp + i * 4) : make_float4(0.f, 0.f, 0.f, 0.f);
                store_perm4(krow, d, kv);
                float4 vv = v ? *(const float4*)(Vp + i * 4) : make_float4(0.f, 0.f, 0.f, 0.f);
                sVT[(d + 0) * FST + pk] = to_tf32(vv.x);
                sVT[(d + 1) * FST + pk] = to_tf32(vv.y);
                sVT[(d + 2) * FST + pk] = to_tf32(vv.z);
                sVT[(d + 3) * FST + pk] = to_tf32(vv.w);
            }
        }
        __syncthreads();

        // QK^T: 16 rows x 64 keys per warp
        float sc[8][4] = {};
        #pragma unroll
        for (int kb = 0; kb < 64; kb += 8) {
            float2 ap0 = *(const float2*)&sQ[(wr + (lane >> 2)) * FST + kb + 2 * (lane & 3)];
            float2 ap1 = *(const float2*)&sQ[(wr + (lane >> 2) + 8) * FST + kb + 2 * (lane & 3)];
            #pragma unroll
            for (int j = 0; j < 8; j++) {
                float2 bp = *(const float2*)&sK[(j * 8 + (lane >> 2)) * FST + kb + 2 * (lane & 3)];
                mma_tf32(sc[j], ap0.x, ap1.x, ap0.y, ap1.y, bp.x, bp.y);
            }
        }

        // softmax in registers, write P to per-warp smem
        bool tail = (k0 + 64 > SLEN);
        {
            float mx0 = -1e30f, mx1 = -1e30f;
            #pragma unroll
            for (int j = 0; j < 8; j++) {
                int col = j * 8 + 2 * (lane & 3);
                float s0 = sc[j][0] * FSC, s1 = sc[j][1] * FSC;
                float s2 = sc[j][2] * FSC, s3 = sc[j][3] * FSC;
                if (tail) {
                    if (k0 + col >= SLEN)     { s0 = -1e30f; s2 = -1e30f; }
                    if (k0 + col + 1 >= SLEN) { s1 = -1e30f; s3 = -1e30f; }
                }
                sc[j][0] = s0; sc[j][1] = s1; sc[j][2] = s2; sc[j][3] = s3;
                mx0 = fmaxf(mx0, fmaxf(s0, s1));
                mx1 = fmaxf(mx1, fmaxf(s2, s3));
            }
            mx0 = fmaxf(mx0, __shfl_xor_sync(0xffffffffu, mx0, 1));
            mx0 = fmaxf(mx0, __shfl_xor_sync(0xffffffffu, mx0, 2));
            mx1 = fmaxf(mx1, __shfl_xor_sync(0xffffffffu, mx1, 1));
            mx1 = fmaxf(mx1, __shfl_xor_sync(0xffffffffu, mx1, 2));
            float mn0 = fmaxf(mrow[0], mx0);
            float mn1 = fmaxf(mrow[1], mx1);
            float sf0 = exp2f(mrow[0] - mn0);
            float sf1 = exp2f(mrow[1] - mn1);
            mrow[0] = mn0; mrow[1] = mn1;
            float sum0 = 0.f, sum1 = 0.f;
            int rl = lane >> 2;
            float* pr0 = &sPw[rl * FST];
            float* pr1 = &sPw[(rl + 8) * FST];
            #pragma unroll
            for (int j = 0; j < 8; j++) {
                int col = j * 8 + 2 * (lane & 3);
                int p0i = pperm(col), p1i = pperm(col + 1);
                float p0 = exp2f(sc[j][0] - mn0); sum0 += p0;
                float p1 = exp2f(sc[j][1] - mn0); sum0 += p1;
                float p2 = exp2f(sc[j][2] - mn1); sum1 += p2;
                float p3 = exp2f(sc[j][3] - mn1); sum1 += p3;
                pr0[p0i] = to_tf32(p0); pr0[p1i] = to_tf32(p1);
                pr1[p0i] = to_tf32(p2); pr1[p1i] = to_tf32(p3);
                o[j][0] *= sf0; o[j][1] *= sf0;
                o[j][2] *= sf1; o[j][3] *= sf1;
            }
            sum0 += __shfl_xor_sync(0xffffffffu, sum0, 1);
            sum0 += __shfl_xor_sync(0xffffffffu, sum0, 2);
            sum1 += __shfl_xor_sync(0xffffffffu, sum1, 1);
            sum1 += __shfl_xor_sync(0xffffffffu, sum1, 2);
            lrow[0] = lrow[0] * sf0 + sum0;
            lrow[1] = lrow[1] * sf1 + sum1;
        }
        __syncwarp();

        // O += P @ V
        #pragma unroll
        for (int kb = 0; kb < 64; kb += 8) {
            float2 ap0 = *(const float2*)&sPw[(lane >> 2) * FST + kb + 2 * (lane & 3)];
            float2 ap1 = *(const float2*)&sPw[((lane >> 2) + 8) * FST + kb + 2 * (lane & 3)];
            #pragma unroll
            for (int j = 0; j < 8; j++) {
                float2 bp = *(const float2*)&sVT[(j * 8 + (lane >> 2)) * FST + kb + 2 * (lane & 3)];
                mma_tf32(o[j], ap0.x, ap1.x, ap0.y, ap1.y, bp.x, bp.y);
            }
        }
    }

    // normalize + store (16 rows per warp)
    {
        int rl = wr + (lane >> 2);
        int q1 = q0 + rl, q2 = q1 + 8;
        float inv0 = 1.f / lrow[0];
        float inv1 = 1.f / lrow[1];
        #pragma unroll
        for (int j = 0; j < 8; j++) {
            int col = h * DHEAD + j * 8 + 2 * (lane & 3);
            if (q1 < SLEN) {
                float2 v = {o[j][0] * inv0, o[j][1] * inv0};
                *(float2*)(AO + ((size_t)(b * SLEN + q1)) * HD + col) = v;
            }
            if (q2 < SLEN) {
                float2 v = {o[j][2] * inv1, o[j][3] * inv1};
                *(float2*)(AO + ((size_t)(b * SLEN + q2)) * HD + col) = v;
            }
        }
    }
}

// ---------------- residual + layernorm (single-pass, warp reductions) ----------------
__global__ void k_lnres(const float* __restrict__ delta,
                        const float* __restrict__ gw, const float* __restrict__ bw) {
    int t = blockIdx.x;
    int d = threadIdx.x;
    int lane = d & 31, warp = d >> 5;
    __shared__ float ws[8], ws2[8];
    float v = g_X[(size_t)t * DMODEL + d] + delta[(size_t)t * DMODEL + d];
    float s = v, s2 = v * v;
    #pragma unroll
    for (int off = 16; off > 0; off >>= 1) {
        s  += __shfl_xor_sync(0xffffffffu, s, off);
        s2 += __shfl_xor_sync(0xffffffffu, s2, off);
    }
    if (lane == 0) { ws[warp] = s; ws2[warp] = s2; }
    __syncthreads();
    float ts = 0.f, ts2 = 0.f;
    #pragma unroll
    for (int w = 0; w < 8; w++) { ts += ws[w]; ts2 += ws2[w]; }
    float mean = ts * (1.0f / DMODEL);
    float var = ts2 * (1.0f / DMODEL) - mean * mean;
    g_X[(size_t)t * DMODEL + d] = (v - mean) * rsqrtf(var + 1e-5f) * gw[d] + bw[d];
}

// ---------------- output heads ----------------
__global__ void k_node_out(const float* __restrict__ w, const float* __restrict__ bias,
                           float* __restrict__ out) {
    int t = blockIdx.x;
    int b = t / NN, i = t % NN;
    __shared__ float row[DMODEL];
    row[threadIdx.x] = g_X[((size_t)(b * SLEN + i)) * DMODEL + threadIdx.x];
    __syncthreads();
    if (threadIdx.x < NFEAT) {
        float acc = bias[threadIdx.x];
        for (int d = 0; d < DMODEL; d++) acc += row[d] * w[d * NFEAT + threadIdx.x];
        out[t * NFEAT + threadIdx.x] = acc;
    }
}

__global__ void k_edge_pre(const float* __restrict__ w, const float* __restrict__ bias) {
    int t = blockIdx.x;
    int b = t / (NN * NN), e = t % (NN * NN);
    __shared__ float row[DMODEL];
    row[threadIdx.x] = g_X[((size_t)(b * SLEN + NN + e)) * DMODEL + threadIdx.x];
    __syncthreads();
    if (threadIdx.x < NEFEAT) {
        float acc = bias[threadIdx.x];
        for (int d = 0; d < DMODEL; d++) acc += row[d] * w[d * NEFEAT + threadIdx.x];
        g_EDG[t * NEFEAT + threadIdx.x] = acc;
    }
}

__global__ void k_edge_sym(float* __restrict__ out) {
    int idx = blockIdx.x * 256 + threadIdx.x;
    const int total = BATCH * NN * NN * NEFEAT;
    if (idx >= total) return;
    int f = idx % NEFEAT;
    int r = idx / NEFEAT;
    int j = r % NN; r /= NN;
    int i = r % NN;
    int b = r / NN;
    float a = g_EDG[(((b * NN + i) * NN + j)) * NEFEAT + f];
    float c = g_EDG[(((b * NN + j) * NN + i)) * NEFEAT + f];
    out[BATCH * NN * NFEAT + idx] = 0.5f * (a + c);
}

// ---------------- launcher ----------------
extern "C" void kernel_launch(void* const* d_in, const int* in_sizes, int n_in,
                              void* d_out, int out_size) {
    const float* graph_emb = (const float*)d_in[0];
    const float* perm      = (const float*)d_in[1];
    const float* pn_w = (const float*)d_in[3];
    const float* pn_b = (const float*)d_in[4];
    const float* pe_w = (const float*)d_in[5];
    const float* pe_b = (const float*)d_in[6];
    const float* no_w = (const float*)d_in[7];
    const float* no_b = (const float*)d_in[8];
    const float* eo_w = (const float*)d_in[9];
    const float* eo_b = (const float*)d_in[10];
    const float* Wq = (const float*)d_in[11];
    const float* bq = (const float*)d_in[12];
    const float* Wk = (const float*)d_in[13];
    const float* bk = (const float*)d_in[14];
    const float* Wv = (const float*)d_in[15];
    const float* bv = (const float*)d_in[16];
    const float* Wo = (const float*)d_in[17];
    const float* bo = (const float*)d_in[18];
    const float* W1 = (const float*)d_in[19];
    const float* b1 = (const float*)d_in[20];
    const float* W2 = (const float*)d_in[21];
    const float* b2 = (const float*)d_in[22];
    const float* ln1g = (const float*)d_in[23];
    const float* ln1b = (const float*)d_in[24];
    const float* ln2g = (const float*)d_in[25];
    const float* ln2b = (const float*)d_in[26];
    float* out = (float*)d_out;

    float *pX, *pQKV, *pAO, *pT, *pFF;
    cudaGetSymbolAddress((void**)&pX,   g_X);
    cudaGetSymbolAddress((void**)&pQKV, g_QKV);
    cudaGetSymbolAddress((void**)&pAO,  g_AO);
    cudaGetSymbolAddress((void**)&pT,   g_T);
    cudaGetSymbolAddress((void**)&pFF,  g_FF);

    const int gemm_smem  = 2 * GSBUF * (int)sizeof(float);
    const int flash_smem = (QT + 64 + 64 + QT) * FST * (int)sizeof(float);
    cudaFuncSetAttribute(k_gemm,  cudaFuncAttributeMaxDynamicSharedMemorySize, gemm_smem);
    cudaFuncSetAttribute(k_flash, cudaFuncAttributeMaxDynamicSharedMemorySize, flash_smem);

    k_pos<<<BATCH * NN, PDIM>>>(perm);
    k_build_x<<<MTOT, DMODEL>>>(graph_emb, pn_w, pn_b, pe_w, pe_b);

    const int M = MTOT;
    const int MG = (M + GBM - 1) / GBM;   // 37
    dim3 gQKV(MG, (3 * HD) / GBN);        // 37 x 24
    dim3 gO  (MG, DMODEL / GBN);          // 37 x 4
    dim3 gF1 (MG, FFDIM / GBN);           // 37 x 16
    dim3 gAtt((SLEN + QT - 1) / QT, NHEAD, BATCH);   // 19 x 8 x 2

    for (int l = 0; l < NLAYER; l++) {
        const float* Wql = Wq + (size_t)l * DMODEL * HD;
        const float* Wkl = Wk + (size_t)l * DMODEL * HD;
        const float* Wvl = Wv + (size_t)l * DMODEL * HD;
        const float* Wol = Wo + (size_t)l * HD * DMODEL;
        const float* W1l = W1 + (size_t)l * DMODEL * FFDIM;
        const float* W2l = W2 + (size_t)l * FFDIM * DMODEL;

        k_gemm<<<gQKV, 256, gemm_smem>>>(pX, Wql, Wkl, Wvl,
                                         bq + l * HD, bk + l * HD, bv + l * HD,
                                         pQKV, M, DMODEL, HD, 3 * HD, 0);
        k_flash<<<gAtt, 256, flash_smem>>>(pQKV, pAO);
        k_gemm<<<gO, 256, gemm_smem>>>(pAO, Wol, Wol, Wol,
                                       bo + l * DMODEL, bo + l * DMODEL, bo + l * DMODEL,
                                       pT, M, HD, DMODEL, DMODEL, 0);
        k_lnres<<<MTOT, DMODEL>>>(pT, ln1g + l * DMODEL, ln1b + l * DMODEL);
        k_gemm<<<gF1, 256, gemm_smem>>>(pX, W1l, W1l, W1l,
                                        b1 + l * FFDIM, b1 + l * FFDIM, b1 + l * FFDIM,
                                        pFF, M, DMODEL, FFDIM, FFDIM, 1);
        k_gemm<<<gO, 256, gemm_smem>>>(pFF, W2l, W2l, W2l,
                                       b2 + l * DMODEL, b2 + l * DMODEL, b2 + l * DMODEL,
                                       pT, M, FFDIM, DMODEL, DMODEL, 0);
        k_lnres<<<MTOT, DMODEL>>>(pT, ln2g + l * DMODEL, ln2b + l * DMODEL);
    }

    k_node_out<<<BATCH * NN, DMODEL>>>(no_w, no_b, out);
    k_edge_pre<<<BATCH * NN * NN, DMODEL>>>(eo_w, eo_b);
    k_edge_sym<<<(BATCH * NN * NN * NEFEAT + 255) / 256, 256>>>(out);
}

// round 14
// speedup vs baseline: 1.5918x; 1.0837x over previous
#include <cuda_runtime.h>
#include <cuda_bf16.h>
#include <math.h>
#include <stdint.h>

#define BATCH 2
#define NN 48
#define DMODEL 256
#define NHEAD 8
#define DHEAD 64
#define HD 512
#define FFDIM 1024
#define NLAYER 4
#define PDIM 32
#define NFEAT 20
#define NEFEAT 5
#define SLEN 2352
#define MTOT (BATCH*SLEN) // 4704

// ---------------- scratch ----------------
__device__ float g_X  [MTOT * DMODEL];
__device__ float g_QKV[MTOT * 3 * HD];
__device__ float g_AO [MTOT * HD];
__device__ float g_T  [MTOT * DMODEL];
__device__ float g_FF [MTOT * FFDIM];
__device__ float g_POS[BATCH * NN * PDIM];
__device__ float g_EDG[BATCH * NN * NN * NEFEAT];

// ---------------- tf32 helpers ----------------
__device__ __forceinline__ float to_tf32(float x) {
    uint32_t u;
    asm("cvt.rna.tf32.f32 %0, %1;" : "=r"(u) : "f"(x));
    return __uint_as_float(u);
}
__device__ __forceinline__ void mma_tf32(float c[4],
    float a0, float a1, float a2, float a3, float b0, float b1) {
    asm volatile(
        "mma.sync.aligned.m16n8k8.row.col.f32.tf32.tf32.f32 "
        "{%0,%1,%2,%3}, {%4,%5,%6,%7}, {%8,%9}, {%0,%1,%2,%3};"
        : "+f"(c[0]), "+f"(c[1]), "+f"(c[2]), "+f"(c[3])
        : "r"(__float_as_uint(a0)), "r"(__float_as_uint(a1)),
          "r"(__float_as_uint(a2)), "r"(__float_as_uint(a3)),
          "r"(__float_as_uint(b0)), "r"(__float_as_uint(b1)));
}
__device__ __forceinline__ int pperm(int k) {
    return (k & ~7) + 2 * (k & 3) + ((k >> 2) & 1);
}
__device__ __forceinline__ void store_perm4(float* row, int k, float4 v) {
    int base = (k & ~7) + ((k >> 2) & 1);
    row[base]     = to_tf32(v.x);
    row[base + 2] = to_tf32(v.y);
    row[base + 4] = to_tf32(v.z);
    row[base + 6] = to_tf32(v.w);
}

// ---------------- positional encoding * perm ----------------
__global__ void k_pos(const float* __restrict__ perm) {
    int b = blockIdx.x / NN, i = blockIdx.x % NN;
    int d = threadIdx.x;
    int k = d >> 1;
    float div = expf(-logf(10000.0f) * (2.0f * (float)k) / (float)PDIM);
    float acc = 0.0f;
    for (int j = 0; j < NN; j++) {
        float ang = (float)j * div;
        float pe = (d & 1) ? cosf(ang) : sinf(ang);
        acc += perm[(b * NN + i) * NN + j] * pe;
    }
    g_POS[(b * NN + i) * PDIM + d] = acc;
}

// ---------------- build initial x ----------------
__global__ void k_build_x(const float* __restrict__ graph_emb,
                          const float* __restrict__ pn_w, const float* __restrict__ pn_b,
                          const float* __restrict__ pe_w, const float* __restrict__ pe_b) {
    int t = blockIdx.x;
    int b = t / SLEN, s = t % SLEN;
    int d = threadIdx.x;
    __shared__ float pi[PDIM], pj[PDIM];
    if (s < NN) {
        if (threadIdx.x < PDIM) pi[threadIdx.x] = g_POS[(b * NN + s) * PDIM + threadIdx.x];
    } else {
        int e = s - NN;
        int i = e / NN, j = e % NN;
        if (threadIdx.x < PDIM) pi[threadIdx.x] = g_POS[(b * NN + i) * PDIM + threadIdx.x];
        else if (threadIdx.x < 2 * PDIM) pj[threadIdx.x - PDIM] = g_POS[(b * NN + j) * PDIM + threadIdx.x - PDIM];
    }
    __syncthreads();
    float acc = graph_emb[b * DMODEL + d];
    if (s < NN) {
        acc += pn_b[d];
        #pragma unroll 8
        for (int p = 0; p < PDIM; p++) acc += pi[p] * pn_w[p * DMODEL + d];
    } else {
        acc += pe_b[d];
        #pragma unroll 8
        for (int p = 0; p < PDIM; p++) {
            acc += pi[p] * pe_w[p * DMODEL + d];
            acc += pj[p] * pe_w[(PDIM + p) * DMODEL + d];
        }
    }
    g_X[(size_t)t * DMODEL + d] = acc;
}

// ---------------- tf32 GEMM, double-buffered, pair-permuted ----------------
#define GBM 128
#define GBN 64
#define GBK 32
#define GSTR 36
#define GSBUF ((GBM + GBN) * GSTR)
__global__ __launch_bounds__(256, 2) void k_gemm(
    const float* __restrict__ A,
    const float* __restrict__ W0, const float* __restrict__ W1, const float* __restrict__ W2,
    const float* __restrict__ B0, const float* __restrict__ B1, const float* __restrict__ B2,
    float* __restrict__ C, int M, int Kin, int Nper, int Nstride, int relu) {
    extern __shared__ float sm[];
    int m0 = blockIdx.x * GBM, n0 = blockIdx.y * GBN;
    int sel = n0 / Nper, nw = n0 % Nper;
    const float* W    = (sel == 0) ? W0 : (sel == 1) ? W1 : W2;
    const float* bias = (sel == 0) ? B0 : (sel == 1) ? B1 : B2;
    int tid = threadIdx.x, lane = tid & 31, wid = tid >> 5;
    int wm = (wid & 3) * 32, wn = (wid >> 2) * 32;
    float c[2][4][4] = {};

    int ar = tid >> 3, ak = (tid & 7) * 4;
    int bk = tid & 31, bnb = (tid >> 5) * 8;

    float4 aR[4], bR0, bR1;
    int nk = Kin / GBK;

    auto gload = [&](int k0) {
        #pragma unroll
        for (int p = 0; p < 4; p++) {
            int row = m0 + ar + p * 32;
            aR[p] = (row < M) ? *(const float4*)(A + (size_t)row * Kin + k0 + ak)
                              : make_float4(0.f, 0.f, 0.f, 0.f);
        }
        const float* wp = W + (size_t)(k0 + bk) * Nper + nw + bnb;
        bR0 = *(const float4*)(wp);
        bR1 = *(const float4*)(wp + 4);
    };
    auto sstore = [&](int s) {
        float* sA = sm + s * GSBUF;
        float* sB = sA + GBM * GSTR;
        #pragma unroll
        for (int p = 0; p < 4; p++)
            store_perm4(&sA[(ar + p * 32) * GSTR], ak, aR[p]);
        int pk = pperm(bk);
        sB[(bnb + 0) * GSTR + pk] = to_tf32(bR0.x);
        sB[(bnb + 1) * GSTR + pk] = to_tf32(bR0.y);
        sB[(bnb + 2) * GSTR + pk] = to_tf32(bR0.z);
        sB[(bnb + 3) * GSTR + pk] = to_tf32(bR0.w);
        sB[(bnb + 4) * GSTR + pk] = to_tf32(bR1.x);
        sB[(bnb + 5) * GSTR + pk] = to_tf32(bR1.y);
        sB[(bnb + 6) * GSTR + pk] = to_tf32(bR1.z);
        sB[(bnb + 7) * GSTR + pk] = to_tf32(bR1.w);
    };

    gload(0);
    sstore(0);
    __syncthreads();

    for (int t = 0; t < nk; t++) {
        if (t + 1 < nk) gload((t + 1) * GBK);
        int s = t & 1;
        const float* sA = sm + s * GSBUF;
        const float* sB = sA + GBM * GSTR;
        #pragma unroll
        for (int kb = 0; kb < GBK; kb += 8) {
            float2 ap[4];
            #pragma unroll
            for (int i = 0; i < 4; i++)
                ap[i] = *(const float2*)&sA[(wm + (lane >> 2) + i * 8) * GSTR + kb + 2 * (lane & 3)];
            #pragma unroll
            for (int j = 0; j < 4; j++) {
                float2 bp = *(const float2*)&sB[(wn + j * 8 + (lane >> 2)) * GSTR + kb + 2 * (lane & 3)];
                mma_tf32(c[0][j], ap[0].x, ap[1].x, ap[0].y, ap[1].y, bp.x, bp.y);
                mma_tf32(c[1][j], ap[2].x, ap[3].x, ap[2].y, ap[3].y, bp.x, bp.y);
            }
        }
        if (t + 1 < nk) sstore(s ^ 1);
        __syncthreads();
    }

    #pragma unroll
    for (int i = 0; i < 2; i++) {
        int r0 = m0 + wm + i * 16 + (lane >> 2);
        #pragma unroll
        for (int j = 0; j < 4; j++) {
            int col = wn + j * 8 + 2 * (lane & 3);
            float b0 = bias[nw + col], b1 = bias[nw + col + 1];
            float v0 = c[i][j][0] + b0, v1 = c[i][j][1] + b1;
            float v2 = c[i][j][2] + b0, v3 = c[i][j][3] + b1;
            if (relu) { v0 = fmaxf(v0, 0.f); v1 = fmaxf(v1, 0.f); v2 = fmaxf(v2, 0.f); v3 = fmaxf(v3, 0.f); }
            if (r0 < M) { float2 o = {v0, v1}; *(float2*)(C + (size_t)r0 * Nstride + n0 + col) = o; }
            if (r0 + 8 < M) { float2 o = {v2, v3}; *(float2*)(C + (size_t)(r0 + 8) * Nstride + n0 + col) = o; }
        }
    }
}

// ---------------- flash attention v6: Q in regs, decoupled PV tiles ----------------
// QT=128, 256 threads. QK/softmax: 8 warps x 16 rows (Q frags in registers).
// PV: 8 warps as 4 row-tiles(32) x 2 col-tiles(32); sf/l via smem.
#define QT 128
#define FST 68
#define FSC (0.125f * 1.44269504088896340736f)
__global__ __launch_bounds__(256, 2) void k_flash(const float* __restrict__ QKV,
                                                  float* __restrict__ AO) {
    extern __shared__ float sm[];
    float* sK   = sm;                      // [64 key][68] pair-perm over d
    float* sVT  = sK  + 64 * FST;          // [64 d][68] pair-perm over key
    float* sP   = sVT + 64 * FST;          // [128 q][68] pair-perm over key
    float* srow = sP  + QT * FST;          // [128] per-tile rescale factor
    float* lfin = srow + QT;               // [128] final l

    int b = blockIdx.z, h = blockIdx.y;
    int q0 = blockIdx.x * QT;
    int tid = threadIdx.x, lane = tid & 31, wid = tid >> 5;
    int wr = wid * 16;                     // softmax/QK row base
    int rbase = (wid >> 1) * 32;           // PV row base
    int cbase = (wid & 1) * 32;            // PV col base
    float* sPw = sP + wr * FST;

    // ---- load Q fragments into registers (once) ----
    // qa[kb] = A-frag for k-chunk kb: {Q[r1][k], Q[r2][k], Q[r1][k+4], Q[r2][k+4]}
    float qa[8][4];
    {
        int r1 = q0 + wr + (lane >> 2);
        int r2 = r1 + 8;
        bool v1 = r1 < SLEN, v2 = r2 < SLEN;
        const float* Q1 = QKV + ((size_t)(b * SLEN + (v1 ? r1 : 0))) * 1536 + h * DHEAD;
        const float* Q2 = QKV + ((size_t)(b * SLEN + (v2 ? r2 : 0))) * 1536 + h * DHEAD;
        #pragma unroll
        for (int kb = 0; kb < 8; kb++) {
            int k = kb * 8 + (lane & 3);
            qa[kb][0] = v1 ? to_tf32(Q1[k])     : 0.f;
            qa[kb][1] = v2 ? to_tf32(Q2[k])     : 0.f;
            qa[kb][2] = v1 ? to_tf32(Q1[k + 4]) : 0.f;
            qa[kb][3] = v2 ? to_tf32(Q2[k + 4]) : 0.f;
        }
    }

    float o[2][4][4] = {};                 // PV accum: 32 rows x 32 cols
    float mrow[2] = {-1e30f, -1e30f};
    float lrow[2] = {0.f, 0.f};

    for (int k0 = 0; k0 < SLEN; k0 += 64) {
        __syncthreads();   // prev PV done; safe to overwrite sK/sVT/sP
        // stage K and V^T: quarter row per thread
        {
            int row = tid >> 2, quar = tid & 3;
            int ki = k0 + row;
            bool v = ki < SLEN;
            const float* Kp = QKV + ((size_t)(b * SLEN + (v ? ki : 0))) * 1536 + HD + h * DHEAD + quar * 16;
            const float* Vp = Kp + HD;
            float* krow = &sK[row * FST];
            int pk = pperm(row);
            #pragma unroll
            for (int i = 0; i < 4; i++) {
                int d = quar * 16 + i * 4;
                float4 kv = v ? *(const float4*)(Kp + i * 4) : make_float4(0.f, 0.f, 0.f, 0.f);
                store_perm4(krow, d, kv);
                float4 vv = v ? *(const float4*)(Vp + i * 4) : make_float4(0.f, 0.f, 0.f, 0.f);
                sVT[(d + 0) * FST + pk] = to_tf32(vv.x);
                sVT[(d + 1) * FST + pk] = to_tf32(vv.y);
                sVT[(d + 2) * FST + pk] = to_tf32(vv.z);
                sVT[(d + 3) * FST + pk] = to_tf32(vv.w);
            }
        }
        __syncthreads();

        // QK^T: 16 rows x 64 keys per warp; A from registers
        float sc[8][4] = {};
        #pragma unroll
        for (int kb = 0; kb < 8; kb++) {
            #pragma unroll
            for (int j = 0; j < 8; j++) {
                float2 bp = *(const float2*)&sK[(j * 8 + (lane >> 2)) * FST + kb * 8 + 2 * (lane & 3)];
                mma_tf32(sc[j], qa[kb][0], qa[kb][1], qa[kb][2], qa[kb][3], bp.x, bp.y);
            }
        }

        // softmax in registers; P + sf to smem
        bool tail = (k0 + 64 > SLEN);
        {
            float mx0 = -1e30f, mx1 = -1e30f;
            #pragma unroll
            for (int j = 0; j < 8; j++) {
                int col = j * 8 + 2 * (lane & 3);
                float s0 = sc[j][0] * FSC, s1 = sc[j][1] * FSC;
                float s2 = sc[j][2] * FSC, s3 = sc[j][3] * FSC;
                if (tail) {
                    if (k0 + col >= SLEN)     { s0 = -1e30f; s2 = -1e30f; }
                    if (k0 + col + 1 >= SLEN) { s1 = -1e30f; s3 = -1e30f; }
                }
                sc[j][0] = s0; sc[j][1] = s1; sc[j][2] = s2; sc[j][3] = s3;
                mx0 = fmaxf(mx0, fmaxf(s0, s1));
                mx1 = fmaxf(mx1, fmaxf(s2, s3));
            }
            mx0 = fmaxf(mx0, __shfl_xor_sync(0xffffffffu, mx0, 1));
            mx0 = fmaxf(mx0, __shfl_xor_sync(0xffffffffu, mx0, 2));
            mx1 = fmaxf(mx1, __shfl_xor_sync(0xffffffffu, mx1, 1));
            mx1 = fmaxf(mx1, __shfl_xor_sync(0xffffffffu, mx1, 2));
            float mn0 = fmaxf(mrow[0], mx0);
            float mn1 = fmaxf(mrow[1], mx1);
            float sf0 = exp2f(mrow[0] - mn0);
            float sf1 = exp2f(mrow[1] - mn1);
            mrow[0] = mn0; mrow[1] = mn1;
            float sum0 = 0.f, sum1 = 0.f;
            int rl = lane >> 2;
            float* pr0 = &sPw[rl * FST];
            float* pr1 = &sPw[(rl + 8) * FST];
            #pragma unroll
            for (int j = 0; j < 8; j++) {
                int col = j * 8 + 2 * (lane & 3);
                int p0i = pperm(col), p1i = pperm(col + 1);
                float p0 = exp2f(sc[j][0] - mn0); sum0 += p0;
                float p1 = exp2f(sc[j][1] - mn0); sum0 += p1;
                float p2 = exp2f(sc[j][2] - mn1); sum1 += p2;
                float p3 = exp2f(sc[j][3] - mn1); sum1 += p3;
                pr0[p0i] = to_tf32(p0); pr0[p1i] = to_tf32(p1);
                pr1[p0i] = to_tf32(p2); pr1[p1i] = to_tf32(p3);
            }
            sum0 += __shfl_xor_sync(0xffffffffu, sum0, 1);
            sum0 += __shfl_xor_sync(0xffffffffu, sum0, 2);
            sum1 += __shfl_xor_sync(0xffffffffu, sum1, 1);
            sum1 += __shfl_xor_sync(0xffffffffu, sum1, 2);
            lrow[0] = lrow[0] * sf0 + sum0;
            lrow[1] = lrow[1] * sf1 + sum1;
            if ((lane & 3) == 0) {
                srow[wr + rl] = sf0;
                srow[wr + rl + 8] = sf1;
            }
        }
        __syncthreads();   // P + srow visible to all warps

        // PV: warp = 32 rows (rbase) x 32 cols (cbase)
        {
            int rl = lane >> 2;
            float f0 = srow[rbase + rl];
            float f1 = srow[rbase + rl + 8];
            float f2 = srow[rbase + 16 + rl];
            float f3 = srow[rbase + 16 + rl + 8];
            #pragma unroll
            for (int j = 0; j < 4; j++) {
                o[0][j][0] *= f0; o[0][j][1] *= f0;
                o[0][j][2] *= f1; o[0][j][3] *= f1;
                o[1][j][0] *= f2; o[1][j][1] *= f2;
                o[1][j][2] *= f3; o[1][j][3] *= f3;
            }
            #pragma unroll
            for (int kb = 0; kb < 8; kb++) {
                float2 ap[4];
                #pragma unroll
                for (int i = 0; i < 4; i++)
                    ap[i] = *(const float2*)&sP[(rbase + rl + i * 8) * FST + kb * 8 + 2 * (lane & 3)];
                #pragma unroll
                for (int j = 0; j < 4; j++) {
                    float2 bp = *(const float2*)&sVT[(cbase + j * 8 + rl) * FST + kb * 8 + 2 * (lane & 3)];
                    mma_tf32(o[0][j], ap[0].x, ap[1].x, ap[0].y, ap[1].y, bp.x, bp.y);
                    mma_tf32(o[1][j], ap[2].x, ap[3].x, ap[2].y, ap[3].y, bp.x, bp.y);
                }
            }
        }
    }

    // publish final l, then normalize + store
    if ((lane & 3) == 0) {
        lfin[wr + (lane >> 2)] = lrow[0];
        lfin[wr + (lane >> 2) + 8] = lrow[1];
    }
    __syncthreads();
    {
        int rl = lane >> 2;
        #pragma unroll
        for (int i = 0; i < 2; i++) {
            int r1 = rbase + 16 * i + rl;
            int r2 = r1 + 8;
            int q1 = q0 + r1, q2 = q0 + r2;
            float inv0 = 1.f / lfin[r1];
            float inv1 = 1.f / lfin[r2];
            #pragma unroll
            for (int j = 0; j < 4; j++) {
                int col = h * DHEAD + cbase + j * 8 + 2 * (lane & 3);
                if (q1 < SLEN) {
                    float2 v = {o[i][j][0] * inv0, o[i][j][1] * inv0};
                    *(float2*)(AO + ((size_t)(b * SLEN + q1)) * HD + col) = v;
                }
                if (q2 < SLEN) {
                    float2 v = {o[i][j][2] * inv1, o[i][j][3] * inv1};
                    *(float2*)(AO + ((size_t)(b * SLEN + q2)) * HD + col) = v;
                }
            }
        }
    }
}

// ---------------- residual + layernorm (single-pass, warp reductions) ----------------
__global__ void k_lnres(const float* __restrict__ delta,
                        const float* __restrict__ gw, const float* __restrict__ bw) {
    int t = blockIdx.x;
    int d = threadIdx.x;
    int lane = d & 31, warp = d >> 5;
    __shared__ float ws[8], ws2[8];
    float v = g_X[(size_t)t * DMODEL + d] + delta[(size_t)t * DMODEL + d];
    float s = v, s2 = v * v;
    #pragma unroll
    for (int off = 16; off > 0; off >>= 1) {
        s  += __shfl_xor_sync(0xffffffffu, s, off);
        s2 += __shfl_xor_sync(0xffffffffu, s2, off);
    }
    if (lane == 0) { ws[warp] = s; ws2[warp] = s2; }
    __syncthreads();
    float ts = 0.f, ts2 = 0.f;
    #pragma unroll
    for (int w = 0; w < 8; w++) { ts += ws[w]; ts2 += ws2[w]; }
    float mean = ts * (1.0f / DMODEL);
    float var = ts2 * (1.0f / DMODEL) - mean * mean;
    g_X[(size_t)t * DMODEL + d] = (v - mean) * rsqrtf(var + 1e-5f) * gw[d] + bw[d];
}

// ---------------- output heads ----------------
__global__ void k_node_out(const float* __restrict__ w, const float* __restrict__ bias,
                           float* __restrict__ out) {
    int t = blockIdx.x;
    int b = t / NN, i = t % NN;
    __shared__ float row[DMODEL];
    row[threadIdx.x] = g_X[((size_t)(b * SLEN + i)) * DMODEL + threadIdx.x];
    __syncthreads();
    if (threadIdx.x < NFEAT) {
        float acc = bias[threadIdx.x];
        for (int d = 0; d < DMODEL; d++) acc += row[d] * w[d * NFEAT + threadIdx.x];
        out[t * NFEAT + threadIdx.x] = acc;
    }
}

__global__ void k_edge_pre(const float* __restrict__ w, const float* __restrict__ bias) {
    int t = blockIdx.x;
    int b = t / (NN * NN), e = t % (NN * NN);
    __shared__ float row[DMODEL];
    row[threadIdx.x] = g_X[((size_t)(b * SLEN + NN + e)) * DMODEL + threadIdx.x];
    __syncthreads();
    if (threadIdx.x < NEFEAT) {
        float acc = bias[threadIdx.x];
        for (int d = 0; d < DMODEL; d++) acc += row[d] * w[d * NEFEAT + threadIdx.x];
        g_EDG[t * NEFEAT + threadIdx.x] = acc;
    }
}

__global__ void k_edge_sym(float* __restrict__ out) {
    int idx = blockIdx.x * 256 + threadIdx.x;
    const int total = BATCH * NN * NN * NEFEAT;
    if (idx >= total) return;
    int f = idx % NEFEAT;
    int r = idx / NEFEAT;
    int j = r % NN; r /= NN;
    int i = r % NN;
    int b = r / NN;
    float a = g_EDG[(((b * NN + i) * NN + j)) * NEFEAT + f];
    float c = g_EDG[(((b * NN + j) * NN + i)) * NEFEAT + f];
    out[BATCH * NN * NFEAT + idx] = 0.5f * (a + c);
}

// ---------------- launcher ----------------
extern "C" void kernel_launch(void* const* d_in, const int* in_sizes, int n_in,
                              void* d_out, int out_size) {
    const float* graph_emb = (const float*)d_in[0];
    const float* perm      = (const float*)d_in[1];
    const float* pn_w = (const float*)d_in[3];
    const float* pn_b = (const float*)d_in[4];
    const float* pe_w = (const float*)d_in[5];
    const float* pe_b = (const float*)d_in[6];
    const float* no_w = (const float*)d_in[7];
    const float* no_b = (const float*)d_in[8];
    const float* eo_w = (const float*)d_in[9];
    const float* eo_b = (const float*)d_in[10];
    const float* Wq = (const float*)d_in[11];
    const float* bq = (const float*)d_in[12];
    const float* Wk = (const float*)d_in[13];
    const float* bk = (const float*)d_in[14];
    const float* Wv = (const float*)d_in[15];
    const float* bv = (const float*)d_in[16];
    const float* Wo = (const float*)d_in[17];
    const float* bo = (const float*)d_in[18];
    const float* W1 = (const float*)d_in[19];
    const float* b1 = (const float*)d_in[20];
    const float* W2 = (const float*)d_in[21];
    const float* b2 = (const float*)d_in[22];
    const float* ln1g = (const float*)d_in[23];
    const float* ln1b = (const float*)d_in[24];
    const float* ln2g = (const float*)d_in[25];
    const float* ln2b = (const float*)d_in[26];
    float* out = (float*)d_out;

    float *pX, *pQKV, *pAO, *pT, *pFF;
    cudaGetSymbolAddress((void**)&pX,   g_X);
    cudaGetSymbolAddress((void**)&pQKV, g_QKV);
    cudaGetSymbolAddress((void**)&pAO,  g_AO);
    cudaGetSymbolAddress((void**)&pT,   g_T);
    cudaGetSymbolAddress((void**)&pFF,  g_FF);

    const int gemm_smem  = 2 * GSBUF * (int)sizeof(float);
    const int flash_smem = ((64 + 64 + QT) * FST + 2 * QT) * (int)sizeof(float);
    cudaFuncSetAttribute(k_gemm,  cudaFuncAttributeMaxDynamicSharedMemorySize, gemm_smem);
    cudaFuncSetAttribute(k_flash, cudaFuncAttributeMaxDynamicSharedMemorySize, flash_smem);

    k_pos<<<BATCH * NN, PDIM>>>(perm);
    k_build_x<<<MTOT, DMODEL>>>(graph_emb, pn_w, pn_b, pe_w, pe_b);

    const int M = MTOT;
    const int MG = (M + GBM - 1) / GBM;   // 37
    dim3 gQKV(MG, (3 * HD) / GBN);        // 37 x 24
    dim3 gO  (MG, DMODEL / GBN);          // 37 x 4
    dim3 gF1 (MG, FFDIM / GBN);           // 37 x 16
    dim3 gAtt((SLEN + QT - 1) / QT, NHEAD, BATCH);   // 19 x 8 x 2

    for (int l = 0; l < NLAYER; l++) {
        const float* Wql = Wq + (size_t)l * DMODEL * HD;
        const float* Wkl = Wk + (size_t)l * DMODEL * HD;
        const float* Wvl = Wv + (size_t)l * DMODEL * HD;
        const float* Wol = Wo + (size_t)l * HD * DMODEL;
        const float* W1l = W1 + (size_t)l * DMODEL * FFDIM;
        const float* W2l = W2 + (size_t)l * FFDIM * DMODEL;

        k_gemm<<<gQKV, 256, gemm_smem>>>(pX, Wql, Wkl, Wvl,
                                         bq + l * HD, bk + l * HD, bv + l * HD,
                                         pQKV, M, DMODEL, HD, 3 * HD, 0);
        k_flash<<<gAtt, 256, flash_smem>>>(pQKV, pAO);
        k_gemm<<<gO, 256, gemm_smem>>>(pAO, Wol, Wol, Wol,
                                       bo + l * DMODEL, bo + l * DMODEL, bo + l * DMODEL,
                                       pT, M, HD, DMODEL, DMODEL, 0);
        k_lnres<<<MTOT, DMODEL>>>(pT, ln1g + l * DMODEL, ln1b + l * DMODEL);
        k_gemm<<<gF1, 256, gemm_smem>>>(pX, W1l, W1l, W1l,
                                        b1 + l * FFDIM, b1 + l * FFDIM, b1 + l * FFDIM,
                                        pFF, M, DMODEL, FFDIM, FFDIM, 1);
        k_gemm<<<gO, 256, gemm_smem>>>(pFF, W2l, W2l, W2l,
                                       b2 + l * DMODEL, b2 + l * DMODEL, b2 + l * DMODEL,
                                       pT, M, FFDIM, DMODEL, DMODEL, 0);
        k_lnres<<<MTOT, DMODEL>>>(pT, ln2g + l * DMODEL, ln2b + l * DMODEL);
    }

    k_node_out<<<BATCH * NN, DMODEL>>>(no_w, no_b, out);
    k_edge_pre<<<BATCH * NN * NN, DMODEL>>>(eo_w, eo_b);
    k_edge_sym<<<(BATCH * NN * NN * NEFEAT + 255) / 256, 256>>>(out);
}

// round 15
// speedup vs baseline: 2.0270x; 1.2735x over previous
#include <cuda_runtime.h>
#include <cuda_bf16.h>
#include <math.h>
#include <stdint.h>

#define BATCH 2
#define NN 48
#define DMODEL 256
#define NHEAD 8
#define DHEAD 64
#define HD 512
#define FFDIM 1024
#define NLAYER 4
#define PDIM 32
#define NFEAT 20
#define NEFEAT 5
#define SLEN 2352
#define MTOT (BATCH*SLEN) // 4704

// ---------------- scratch ----------------
__device__ float g_X  [MTOT * DMODEL];
__device__ float g_QKV[MTOT * 3 * HD];
__device__ float g_AO [MTOT * HD];
__device__ float g_T  [MTOT * DMODEL];
__device__ float g_FF [MTOT * FFDIM];
__device__ float g_POS[BATCH * NN * PDIM];
__device__ float g_EDG[BATCH * NN * NN * NEFEAT];

// ---------------- helpers ----------------
__device__ __forceinline__ float to_tf32(float x) {
    uint32_t u;
    asm("cvt.rna.tf32.f32 %0, %1;" : "=r"(u) : "f"(x));
    return __uint_as_float(u);
}
__device__ __forceinline__ void mma_tf32(float c[4],
    float a0, float a1, float a2, float a3, float b0, float b1) {
    asm volatile(
        "mma.sync.aligned.m16n8k8.row.col.f32.tf32.tf32.f32 "
        "{%0,%1,%2,%3}, {%4,%5,%6,%7}, {%8,%9}, {%0,%1,%2,%3};"
        : "+f"(c[0]), "+f"(c[1]), "+f"(c[2]), "+f"(c[3])
        : "r"(__float_as_uint(a0)), "r"(__float_as_uint(a1)),
          "r"(__float_as_uint(a2)), "r"(__float_as_uint(a3)),
          "r"(__float_as_uint(b0)), "r"(__float_as_uint(b1)));
}
__device__ __forceinline__ void mma_bf16(float c[4],
    uint32_t a0, uint32_t a1, uint32_t a2, uint32_t a3,
    uint32_t b0, uint32_t b1) {
    asm volatile(
        "mma.sync.aligned.m16n8k16.row.col.f32.bf16.bf16.f32 "
        "{%0,%1,%2,%3}, {%4,%5,%6,%7}, {%8,%9}, {%0,%1,%2,%3};"
        : "+f"(c[0]), "+f"(c[1]), "+f"(c[2]), "+f"(c[3])
        : "r"(a0), "r"(a1), "r"(a2), "r"(a3), "r"(b0), "r"(b1));
}
// pack {lo, hi} floats into bf16x2 (lo = first k, hi = second k)
__device__ __forceinline__ uint32_t pack_bf16(float lo, float hi) {
    uint32_t r;
    asm("cvt.rn.bf16x2.f32 %0, %1, %2;" : "=r"(r) : "f"(hi), "f"(lo));
    return r;
}
__device__ __forceinline__ int pperm(int k) {
    return (k & ~7) + 2 * (k & 3) + ((k >> 2) & 1);
}
__device__ __forceinline__ void store_perm4(float* row, int k, float4 v) {
    int base = (k & ~7) + ((k >> 2) & 1);
    row[base]     = to_tf32(v.x);
    row[base + 2] = to_tf32(v.y);
    row[base + 4] = to_tf32(v.z);
    row[base + 6] = to_tf32(v.w);
}

// ---------------- positional encoding * perm ----------------
__global__ void k_pos(const float* __restrict__ perm) {
    int b = blockIdx.x / NN, i = blockIdx.x % NN;
    int d = threadIdx.x;
    int k = d >> 1;
    float div = expf(-logf(10000.0f) * (2.0f * (float)k) / (float)PDIM);
    float acc = 0.0f;
    for (int j = 0; j < NN; j++) {
        float ang = (float)j * div;
        float pe = (d & 1) ? cosf(ang) : sinf(ang);
        acc += perm[(b * NN + i) * NN + j] * pe;
    }
    g_POS[(b * NN + i) * PDIM + d] = acc;
}

// ---------------- build initial x ----------------
__global__ void k_build_x(const float* __restrict__ graph_emb,
                          const float* __restrict__ pn_w, const float* __restrict__ pn_b,
                          const float* __restrict__ pe_w, const float* __restrict__ pe_b) {
    int t = blockIdx.x;
    int b = t / SLEN, s = t % SLEN;
    int d = threadIdx.x;
    __shared__ float pi[PDIM], pj[PDIM];
    if (s < NN) {
        if (threadIdx.x < PDIM) pi[threadIdx.x] = g_POS[(b * NN + s) * PDIM + threadIdx.x];
    } else {
        int e = s - NN;
        int i = e / NN, j = e % NN;
        if (threadIdx.x < PDIM) pi[threadIdx.x] = g_POS[(b * NN + i) * PDIM + threadIdx.x];
        else if (threadIdx.x < 2 * PDIM) pj[threadIdx.x - PDIM] = g_POS[(b * NN + j) * PDIM + threadIdx.x - PDIM];
    }
    __syncthreads();
    float acc = graph_emb[b * DMODEL + d];
    if (s < NN) {
        acc += pn_b[d];
        #pragma unroll 8
        for (int p = 0; p < PDIM; p++) acc += pi[p] * pn_w[p * DMODEL + d];
    } else {
        acc += pe_b[d];
        #pragma unroll 8
        for (int p = 0; p < PDIM; p++) {
            acc += pi[p] * pe_w[p * DMODEL + d];
            acc += pj[p] * pe_w[(PDIM + p) * DMODEL + d];
        }
    }
    g_X[(size_t)t * DMODEL + d] = acc;
}

// ---------------- tf32 GEMM, double-buffered, pair-permuted ----------------
#define GBM 128
#define GBN 64
#define GBK 32
#define GSTR 36
#define GSBUF ((GBM + GBN) * GSTR)
__global__ __launch_bounds__(256, 2) void k_gemm(
    const float* __restrict__ A,
    const float* __restrict__ W0, const float* __restrict__ W1, const float* __restrict__ W2,
    const float* __restrict__ B0, const float* __restrict__ B1, const float* __restrict__ B2,
    float* __restrict__ C, int M, int Kin, int Nper, int Nstride, int relu) {
    extern __shared__ float sm[];
    int m0 = blockIdx.x * GBM, n0 = blockIdx.y * GBN;
    int sel = n0 / Nper, nw = n0 % Nper;
    const float* W    = (sel == 0) ? W0 : (sel == 1) ? W1 : W2;
    const float* bias = (sel == 0) ? B0 : (sel == 1) ? B1 : B2;
    int tid = threadIdx.x, lane = tid & 31, wid = tid >> 5;
    int wm = (wid & 3) * 32, wn = (wid >> 2) * 32;
    float c[2][4][4] = {};

    int ar = tid >> 3, ak = (tid & 7) * 4;
    int bk = tid & 31, bnb = (tid >> 5) * 8;

    float4 aR[4], bR0, bR1;
    int nk = Kin / GBK;

    auto gload = [&](int k0) {
        #pragma unroll
        for (int p = 0; p < 4; p++) {
            int row = m0 + ar + p * 32;
            aR[p] = (row < M) ? *(const float4*)(A + (size_t)row * Kin + k0 + ak)
                              : make_float4(0.f, 0.f, 0.f, 0.f);
        }
        const float* wp = W + (size_t)(k0 + bk) * Nper + nw + bnb;
        bR0 = *(const float4*)(wp);
        bR1 = *(const float4*)(wp + 4);
    };
    auto sstore = [&](int s) {
        float* sA = sm + s * GSBUF;
        float* sB = sA + GBM * GSTR;
        #pragma unroll
        for (int p = 0; p < 4; p++)
            store_perm4(&sA[(ar + p * 32) * GSTR], ak, aR[p]);
        int pk = pperm(bk);
        sB[(bnb + 0) * GSTR + pk] = to_tf32(bR0.x);
        sB[(bnb + 1) * GSTR + pk] = to_tf32(bR0.y);
        sB[(bnb + 2) * GSTR + pk] = to_tf32(bR0.z);
        sB[(bnb + 3) * GSTR + pk] = to_tf32(bR0.w);
        sB[(bnb + 4) * GSTR + pk] = to_tf32(bR1.x);
        sB[(bnb + 5) * GSTR + pk] = to_tf32(bR1.y);
        sB[(bnb + 6) * GSTR + pk] = to_tf32(bR1.z);
        sB[(bnb + 7) * GSTR + pk] = to_tf32(bR1.w);
    };

    gload(0);
    sstore(0);
    __syncthreads();

    for (int t = 0; t < nk; t++) {
        if (t + 1 < nk) gload((t + 1) * GBK);
        int s = t & 1;
        const float* sA = sm + s * GSBUF;
        const float* sB = sA + GBM * GSTR;
        #pragma unroll
        for (int kb = 0; kb < GBK; kb += 8) {
            float2 ap[4];
            #pragma unroll
            for (int i = 0; i < 4; i++)
                ap[i] = *(const float2*)&sA[(wm + (lane >> 2) + i * 8) * GSTR + kb + 2 * (lane & 3)];
            #pragma unroll
            for (int j = 0; j < 4; j++) {
                float2 bp = *(const float2*)&sB[(wn + j * 8 + (lane >> 2)) * GSTR + kb + 2 * (lane & 3)];
                mma_tf32(c[0][j], ap[0].x, ap[1].x, ap[0].y, ap[1].y, bp.x, bp.y);
                mma_tf32(c[1][j], ap[2].x, ap[3].x, ap[2].y, ap[3].y, bp.x, bp.y);
            }
        }
        if (t + 1 < nk) sstore(s ^ 1);
        __syncthreads();
    }

    #pragma unroll
    for (int i = 0; i < 2; i++) {
        int r0 = m0 + wm + i * 16 + (lane >> 2);
        #pragma unroll
        for (int j = 0; j < 4; j++) {
            int col = wn + j * 8 + 2 * (lane & 3);
            float b0 = bias[nw + col], b1 = bias[nw + col + 1];
            float v0 = c[i][j][0] + b0, v1 = c[i][j][1] + b1;
            float v2 = c[i][j][2] + b0, v3 = c[i][j][3] + b1;
            if (relu) { v0 = fmaxf(v0, 0.f); v1 = fmaxf(v1, 0.f); v2 = fmaxf(v2, 0.f); v3 = fmaxf(v3, 0.f); }
            if (r0 < M) { float2 o = {v0, v1}; *(float2*)(C + (size_t)r0 * Nstride + n0 + col) = o; }
            if (r0 + 8 < M) { float2 o = {v2, v3}; *(float2*)(C + (size_t)(r0 + 8) * Nstride + n0 + col) = o; }
        }
    }
}

// ---------------- flash attention v7: tf32 QK (Q in regs) + bf16 PV (P in regs) ----
// QT=128, 256 threads, 8 warps x 16 rows, fully warp-local softmax/PV.
// V staged as bf16x2 key-pairs: sVTb[32 pairs][72] (stride 72 -> conflict-free).
#define QT 128
#define FST 68
#define VSTR 72
#define FSC (0.125f * 1.44269504088896340736f)
__global__ __launch_bounds__(256, 2) void k_flash(const float* __restrict__ QKV,
                                                  float* __restrict__ AO) {
    extern __shared__ float sm[];
    float* sK = sm;                                 // [64 key][68] tf32 pair-perm over d
    uint32_t* sVTb = (uint32_t*)(sK + 64 * FST);    // [32 key-pairs][72] bf16x2 {2p, 2p+1}

    int b = blockIdx.z, h = blockIdx.y;
    int q0 = blockIdx.x * QT;
    int tid = threadIdx.x, lane = tid & 31, wid = tid >> 5;
    int wr = wid * 16;

    // ---- Q fragments in registers (loaded once) ----
    float qa[8][4];
    {
        int r1 = q0 + wr + (lane >> 2);
        int r2 = r1 + 8;
        bool v1 = r1 < SLEN, v2 = r2 < SLEN;
        const float* Q1 = QKV + ((size_t)(b * SLEN + (v1 ? r1 : 0))) * 1536 + h * DHEAD;
        const float* Q2 = QKV + ((size_t)(b * SLEN + (v2 ? r2 : 0))) * 1536 + h * DHEAD;
        #pragma unroll
        for (int kb = 0; kb < 8; kb++) {
            int k = kb * 8 + (lane & 3);
            qa[kb][0] = v1 ? to_tf32(Q1[k])     : 0.f;
            qa[kb][1] = v2 ? to_tf32(Q2[k])     : 0.f;
            qa[kb][2] = v1 ? to_tf32(Q1[k + 4]) : 0.f;
            qa[kb][3] = v2 ? to_tf32(Q2[k + 4]) : 0.f;
        }
    }

    float o[8][4] = {};
    float mrow[2] = {-1e30f, -1e30f};
    float lrow[2] = {0.f, 0.f};

    for (int k0 = 0; k0 < SLEN; k0 += 64) {
        __syncthreads();
        // ---- stage K (tf32, pair-perm over d): quarter row per thread ----
        {
            int row = tid >> 2, quar = tid & 3;
            int ki = k0 + row;
            bool v = ki < SLEN;
            const float* Kp = QKV + ((size_t)(b * SLEN + (v ? ki : 0))) * 1536 + HD + h * DHEAD + quar * 16;
            float* krow = &sK[row * FST];
            #pragma unroll
            for (int i = 0; i < 4; i++) {
                float4 kv = v ? *(const float4*)(Kp + i * 4) : make_float4(0.f, 0.f, 0.f, 0.f);
                store_perm4(krow, quar * 16 + i * 4, kv);
            }
        }
        // ---- stage V as bf16x2 key pairs: 8 threads per pair ----
        {
            int p = tid >> 3;                 // 0..31 key pair
            int c8 = (tid & 7) * 8;           // col base
            int k1 = k0 + 2 * p, k2 = k1 + 1;
            bool v1 = k1 < SLEN, v2 = k2 < SLEN;
            const float* V1 = QKV + ((size_t)(b * SLEN + (v1 ? k1 : 0))) * 1536 + 2 * HD + h * DHEAD + c8;
            const float* V2 = QKV + ((size_t)(b * SLEN + (v2 ? k2 : 0))) * 1536 + 2 * HD + h * DHEAD + c8;
            float4 a0 = v1 ? *(const float4*)(V1)     : make_float4(0.f, 0.f, 0.f, 0.f);
            float4 a1 = v1 ? *(const float4*)(V1 + 4) : make_float4(0.f, 0.f, 0.f, 0.f);
            float4 b0 = v2 ? *(const float4*)(V2)     : make_float4(0.f, 0.f, 0.f, 0.f);
            float4 b1 = v2 ? *(const float4*)(V2 + 4) : make_float4(0.f, 0.f, 0.f, 0.f);
            uint32_t* dst = &sVTb[p * VSTR + c8];
            dst[0] = pack_bf16(a0.x, b0.x);
            dst[1] = pack_bf16(a0.y, b0.y);
            dst[2] = pack_bf16(a0.z, b0.z);
            dst[3] = pack_bf16(a0.w, b0.w);
            dst[4] = pack_bf16(a1.x, b1.x);
            dst[5] = pack_bf16(a1.y, b1.y);
            dst[6] = pack_bf16(a1.z, b1.z);
            dst[7] = pack_bf16(a1.w, b1.w);
        }
        __syncthreads();

        // ---- QK^T: 16 rows x 64 keys per warp, A from registers ----
        float sc[8][4] = {};
        #pragma unroll
        for (int kb = 0; kb < 8; kb++) {
            #pragma unroll
            for (int j = 0; j < 8; j++) {
                float2 bp = *(const float2*)&sK[(j * 8 + (lane >> 2)) * FST + kb * 8 + 2 * (lane & 3)];
                mma_tf32(sc[j], qa[kb][0], qa[kb][1], qa[kb][2], qa[kb][3], bp.x, bp.y);
            }
        }

        // ---- softmax (warp-local): sc becomes P (fp32) ----
        bool tail = (k0 + 64 > SLEN);
        {
            float mx0 = -1e30f, mx1 = -1e30f;
            #pragma unroll
            for (int j = 0; j < 8; j++) {
                int col = j * 8 + 2 * (lane & 3);
                float s0 = sc[j][0] * FSC, s1 = sc[j][1] * FSC;
                float s2 = sc[j][2] * FSC, s3 = sc[j][3] * FSC;
                if (tail) {
                    if (k0 + col >= SLEN)     { s0 = -1e30f; s2 = -1e30f; }
                    if (k0 + col + 1 >= SLEN) { s1 = -1e30f; s3 = -1e30f; }
                }
                sc[j][0] = s0; sc[j][1] = s1; sc[j][2] = s2; sc[j][3] = s3;
                mx0 = fmaxf(mx0, fmaxf(s0, s1));
                mx1 = fmaxf(mx1, fmaxf(s2, s3));
            }
            mx0 = fmaxf(mx0, __shfl_xor_sync(0xffffffffu, mx0, 1));
            mx0 = fmaxf(mx0, __shfl_xor_sync(0xffffffffu, mx0, 2));
            mx1 = fmaxf(mx1, __shfl_xor_sync(0xffffffffu, mx1, 1));
            mx1 = fmaxf(mx1, __shfl_xor_sync(0xffffffffu, mx1, 2));
            float mn0 = fmaxf(mrow[0], mx0);
            float mn1 = fmaxf(mrow[1], mx1);
            float sf0 = exp2f(mrow[0] - mn0);
            float sf1 = exp2f(mrow[1] - mn1);
            mrow[0] = mn0; mrow[1] = mn1;
            float sum0 = 0.f, sum1 = 0.f;
            #pragma unroll
            for (int j = 0; j < 8; j++) {
                float p0 = exp2f(sc[j][0] - mn0); sum0 += p0;
                float p1 = exp2f(sc[j][1] - mn0); sum0 += p1;
                float p2 = exp2f(sc[j][2] - mn1); sum1 += p2;
                float p3 = exp2f(sc[j][3] - mn1); sum1 += p3;
                sc[j][0] = p0; sc[j][1] = p1; sc[j][2] = p2; sc[j][3] = p3;
                o[j][0] *= sf0; o[j][1] *= sf0;
                o[j][2] *= sf1; o[j][3] *= sf1;
            }
            sum0 += __shfl_xor_sync(0xffffffffu, sum0, 1);
            sum0 += __shfl_xor_sync(0xffffffffu, sum0, 2);
            sum1 += __shfl_xor_sync(0xffffffffu, sum1, 1);
            sum1 += __shfl_xor_sync(0xffffffffu, sum1, 2);
            lrow[0] = lrow[0] * sf0 + sum0;
            lrow[1] = lrow[1] * sf1 + sum1;
        }

        // ---- PV (bf16 m16n8k16): P C-frag -> A-frag in registers ----
        #pragma unroll
        for (int kc = 0; kc < 4; kc++) {
            uint32_t pa0 = pack_bf16(sc[2 * kc][0],     sc[2 * kc][1]);
            uint32_t pa1 = pack_bf16(sc[2 * kc][2],     sc[2 * kc][3]);
            uint32_t pa2 = pack_bf16(sc[2 * kc + 1][0], sc[2 * kc + 1][1]);
            uint32_t pa3 = pack_bf16(sc[2 * kc + 1][2], sc[2 * kc + 1][3]);
            int pr0 = (kc * 8 + (lane & 3)) * VSTR + (lane >> 2);
            int pr1 = pr0 + 4 * VSTR;
            #pragma unroll
            for (int j = 0; j < 8; j++) {
                uint32_t vb0 = sVTb[pr0 + j * 8];
                uint32_t vb1 = sVTb[pr1 + j * 8];
                mma_bf16(o[j], pa0, pa1, pa2, pa3, vb0, vb1);
            }
        }
    }

    // ---- normalize + store (16 rows per warp) ----
    {
        int rl = wr + (lane >> 2);
        int q1 = q0 + rl, q2 = q1 + 8;
        float inv0 = 1.f / lrow[0];
        float inv1 = 1.f / lrow[1];
        #pragma unroll
        for (int j = 0; j < 8; j++) {
            int col = h * DHEAD + j * 8 + 2 * (lane & 3);
            if (q1 < SLEN) {
                float2 v = {o[j][0] * inv0, o[j][1] * inv0};
                *(float2*)(AO + ((size_t)(b * SLEN + q1)) * HD + col) = v;
            }
            if (q2 < SLEN) {
                float2 v = {o[j][2] * inv1, o[j][3] * inv1};
                *(float2*)(AO + ((size_t)(b * SLEN + q2)) * HD + col) = v;
            }
        }
    }
}

// ---------------- residual + layernorm (single-pass, warp reductions) ----------------
__global__ void k_lnres(const float* __restrict__ delta,
                        const float* __restrict__ gw, const float* __restrict__ bw) {
    int t = blockIdx.x;
    int d = threadIdx.x;
    int lane = d & 31, warp = d >> 5;
    __shared__ float ws[8], ws2[8];
    float v = g_X[(size_t)t * DMODEL + d] + delta[(size_t)t * DMODEL + d];
    float s = v, s2 = v * v;
    #pragma unroll
    for (int off = 16; off > 0; off >>= 1) {
        s  += __shfl_xor_sync(0xffffffffu, s, off);
        s2 += __shfl_xor_sync(0xffffffffu, s2, off);
    }
    if (lane == 0) { ws[warp] = s; ws2[warp] = s2; }
    __syncthreads();
    float ts = 0.f, ts2 = 0.f;
    #pragma unroll
    for (int w = 0; w < 8; w++) { ts += ws[w]; ts2 += ws2[w]; }
    float mean = ts * (1.0f / DMODEL);
    float var = ts2 * (1.0f / DMODEL) - mean * mean;
    g_X[(size_t)t * DMODEL + d] = (v - mean) * rsqrtf(var + 1e-5f) * gw[d] + bw[d];
}

// ---------------- output heads ----------------
__global__ void k_node_out(const float* __restrict__ w, const float* __restrict__ bias,
                           float* __restrict__ out) {
    int t = blockIdx.x;
    int b = t / NN, i = t % NN;
    __shared__ float row[DMODEL];
    row[threadIdx.x] = g_X[((size_t)(b * SLEN + i)) * DMODEL + threadIdx.x];
    __syncthreads();
    if (threadIdx.x < NFEAT) {
        float acc = bias[threadIdx.x];
        for (int d = 0; d < DMODEL; d++) acc += row[d] * w[d * NFEAT + threadIdx.x];
        out[t * NFEAT + threadIdx.x] = acc;
    }
}

__global__ void k_edge_pre(const float* __restrict__ w, const float* __restrict__ bias) {
    int t = blockIdx.x;
    int b = t / (NN * NN), e = t % (NN * NN);
    __shared__ float row[DMODEL];
    row[threadIdx.x] = g_X[((size_t)(b * SLEN + NN + e)) * DMODEL + threadIdx.x];
    __syncthreads();
    if (threadIdx.x < NEFEAT) {
        float acc = bias[threadIdx.x];
        for (int d = 0; d < DMODEL; d++) acc += row[d] * w[d * NEFEAT + threadIdx.x];
        g_EDG[t * NEFEAT + threadIdx.x] = acc;
    }
}

__global__ void k_edge_sym(float* __restrict__ out) {
    int idx = blockIdx.x * 256 + threadIdx.x;
    const int total = BATCH * NN * NN * NEFEAT;
    if (idx >= total) return;
    int f = idx % NEFEAT;
    int r = idx / NEFEAT;
    int j = r % NN; r /= NN;
    int i = r % NN;
    int b = r / NN;
    float a = g_EDG[(((b * NN + i) * NN + j)) * NEFEAT + f];
    float c = g_EDG[(((b * NN + j) * NN + i)) * NEFEAT + f];
    out[BATCH * NN * NFEAT + idx] = 0.5f * (a + c);
}

// ---------------- launcher ----------------
extern "C" void kernel_launch(void* const* d_in, const int* in_sizes, int n_in,
                              void* d_out, int out_size) {
    const float* graph_emb = (const float*)d_in[0];
    const float* perm      = (const float*)d_in[1];
    const float* pn_w = (const float*)d_in[3];
    const float* pn_b = (const float*)d_in[4];
    const float* pe_w = (const float*)d_in[5];
    const float* pe_b = (const float*)d_in[6];
    const float* no_w = (const float*)d_in[7];
    const float* no_b = (const float*)d_in[8];
    const float* eo_w = (const float*)d_in[9];
    const float* eo_b = (const float*)d_in[10];
    const float* Wq = (const float*)d_in[11];
    const float* bq = (const float*)d_in[12];
    const float* Wk = (const float*)d_in[13];
    const float* bk = (const float*)d_in[14];
    const float* Wv = (const float*)d_in[15];
    const float* bv = (const float*)d_in[16];
    const float* Wo = (const float*)d_in[17];
    const float* bo = (const float*)d_in[18];
    const float* W1 = (const float*)d_in[19];
    const float* b1 = (const float*)d_in[20];
    const float* W2 = (const float*)d_in[21];
    const float* b2 = (const float*)d_in[22];
    const float* ln1g = (const float*)d_in[23];
    const float* ln1b = (const float*)d_in[24];
    const float* ln2g = (const float*)d_in[25];
    const float* ln2b = (const float*)d_in[26];
    float* out = (float*)d_out;

    float *pX, *pQKV, *pAO, *pT, *pFF;
    cudaGetSymbolAddress((void**)&pX,   g_X);
    cudaGetSymbolAddress((void**)&pQKV, g_QKV);
    cudaGetSymbolAddress((void**)&pAO,  g_AO);
    cudaGetSymbolAddress((void**)&pT,   g_T);
    cudaGetSymbolAddress((void**)&pFF,  g_FF);

    const int gemm_smem  = 2 * GSBUF * (int)sizeof(float);
    const int flash_smem = 64 * FST * (int)sizeof(float) + 32 * VSTR * (int)sizeof(uint32_t);
    cudaFuncSetAttribute(k_gemm,  cudaFuncAttributeMaxDynamicSharedMemorySize, gemm_smem);
    cudaFuncSetAttribute(k_flash, cudaFuncAttributeMaxDynamicSharedMemorySize, flash_smem);

    k_pos<<<BATCH * NN, PDIM>>>(perm);
    k_build_x<<<MTOT, DMODEL>>>(graph_emb, pn_w, pn_b, pe_w, pe_b);

    const int M = MTOT;
    const int MG = (M + GBM - 1) / GBM;   // 37
    dim3 gQKV(MG, (3 * HD) / GBN);        // 37 x 24
    dim3 gO  (MG, DMODEL / GBN);          // 37 x 4
    dim3 gF1 (MG, FFDIM / GBN);           // 37 x 16
    dim3 gAtt((SLEN + QT - 1) / QT, NHEAD, BATCH);   // 19 x 8 x 2

    for (int l = 0; l < NLAYER; l++) {
        const float* Wql = Wq + (size_t)l * DMODEL * HD;
        const float* Wkl = Wk + (size_t)l * DMODEL * HD;
        const float* Wvl = Wv + (size_t)l * DMODEL * HD;
        const float* Wol = Wo + (size_t)l * HD * DMODEL;
        const float* W1l = W1 + (size_t)l * DMODEL * FFDIM;
        const float* W2l = W2 + (size_t)l * FFDIM * DMODEL;

        k_gemm<<<gQKV, 256, gemm_smem>>>(pX, Wql, Wkl, Wvl,
                                         bq + l * HD, bk + l * HD, bv + l * HD,
                                         pQKV, M, DMODEL, HD, 3 * HD, 0);
        k_flash<<<gAtt, 256, flash_smem>>>(pQKV, pAO);
        k_gemm<<<gO, 256, gemm_smem>>>(pAO, Wol, Wol, Wol,
                                       bo + l * DMODEL, bo + l * DMODEL, bo + l * DMODEL,
                                       pT, M, HD, DMODEL, DMODEL, 0);
        k_lnres<<<MTOT, DMODEL>>>(pT, ln1g + l * DMODEL, ln1b + l * DMODEL);
        k_gemm<<<gF1, 256, gemm_smem>>>(pX, W1l, W1l, W1l,
                                        b1 + l * FFDIM, b1 + l * FFDIM, b1 + l * FFDIM,
                                        pFF, M, DMODEL, FFDIM, FFDIM, 1);
        k_gemm<<<gO, 256, gemm_smem>>>(pFF, W2l, W2l, W2l,
                                       b2 + l * DMODEL, b2 + l * DMODEL, b2 + l * DMODEL,
                                       pT, M, FFDIM, DMODEL, DMODEL, 0);
        k_lnres<<<MTOT, DMODEL>>>(pT, ln2g + l * DMODEL, ln2b + l * DMODEL);
    }

    k_node_out<<<BATCH * NN, DMODEL>>>(no_w, no_b, out);
    k_edge_pre<<<BATCH * NN * NN, DMODEL>>>(eo_w, eo_b);
    k_edge_sym<<<(BATCH * NN * NN * NEFEAT + 255) / 256, 256>>>(out);
}